// round 1
// baseline (speedup 1.0000x reference)
#include <cuda_runtime.h>
#include <math.h>

#define BB 2
#define SS 2048
#define EE 1024
#define HH 16
#define HD 64
#define NN (BB*SS)       // 4096 tokens
#define F3 (3*EE)        // 3072
#define QK_SCALE 0.125f  // HD^-0.5

// Scratch (device globals; no runtime allocation allowed)
__device__ float g_qkv[(size_t)NN * F3];   // [4096, 3072]  q|k|v
__device__ float g_attn[(size_t)NN * EE];  // attn output before out-proj, [B,S,E] layout

// ---------------------------------------------------------------------------
// SGEMM (NT): C[M,N] = A[M,K] * W[N,K]^T + bias[N]
// BM=BN=128, BK=8, 256 threads, 8x8 microtile per thread.
// M,N multiples of 128; K multiple of 8 (true for all our shapes).
// ---------------------------------------------------------------------------
__global__ void __launch_bounds__(256) sgemm_nt_bias(
    const float* __restrict__ A, const float* __restrict__ W,
    const float* __restrict__ bias, float* __restrict__ C,
    int M, int Nn, int K)
{
    __shared__ __align__(16) float As[8 * 128];
    __shared__ __align__(16) float Bs[8 * 128];

    const int tid = threadIdx.x;
    const int tx = tid & 15;       // 0..15 -> N direction
    const int ty = tid >> 4;       // 0..15 -> M direction
    const int m0 = blockIdx.y * 128;
    const int n0 = blockIdx.x * 128;

    // load mapping: one float4 per thread per operand per k-step
    const int lr = tid >> 1;            // 0..127 row within tile
    const int lc = (tid & 1) * 4;       // 0 or 4

    const float* Ap = A + (size_t)(m0 + lr) * K + lc;
    const float* Wp = W + (size_t)(n0 + lr) * K + lc;

    float acc[8][8];
#pragma unroll
    for (int i = 0; i < 8; i++)
#pragma unroll
        for (int j = 0; j < 8; j++) acc[i][j] = 0.f;

    for (int k0 = 0; k0 < K; k0 += 8) {
        float4 a4 = *(const float4*)(Ap + k0);
        float4 b4 = *(const float4*)(Wp + k0);
        As[(lc + 0) * 128 + lr] = a4.x;
        As[(lc + 1) * 128 + lr] = a4.y;
        As[(lc + 2) * 128 + lr] = a4.z;
        As[(lc + 3) * 128 + lr] = a4.w;
        Bs[(lc + 0) * 128 + lr] = b4.x;
        Bs[(lc + 1) * 128 + lr] = b4.y;
        Bs[(lc + 2) * 128 + lr] = b4.z;
        Bs[(lc + 3) * 128 + lr] = b4.w;
        __syncthreads();

#pragma unroll
        for (int kk = 0; kk < 8; kk++) {
            float4 af0 = *(const float4*)(As + kk * 128 + ty * 8);
            float4 af1 = *(const float4*)(As + kk * 128 + ty * 8 + 4);
            float4 bf0 = *(const float4*)(Bs + kk * 128 + tx * 8);
            float4 bf1 = *(const float4*)(Bs + kk * 128 + tx * 8 + 4);
            float a[8] = {af0.x, af0.y, af0.z, af0.w, af1.x, af1.y, af1.z, af1.w};
            float b[8] = {bf0.x, bf0.y, bf0.z, bf0.w, bf1.x, bf1.y, bf1.z, bf1.w};
#pragma unroll
            for (int i = 0; i < 8; i++)
#pragma unroll
                for (int j = 0; j < 8; j++) acc[i][j] = fmaf(a[i], b[j], acc[i][j]);
        }
        __syncthreads();
    }

    // epilogue: add bias, write
    float4 bb0 = *(const float4*)(bias + n0 + tx * 8);
    float4 bb1 = *(const float4*)(bias + n0 + tx * 8 + 4);
    const float bv[8] = {bb0.x, bb0.y, bb0.z, bb0.w, bb1.x, bb1.y, bb1.z, bb1.w};
#pragma unroll
    for (int i = 0; i < 8; i++) {
        float* crow = C + (size_t)(m0 + ty * 8 + i) * Nn + n0 + tx * 8;
        float4 c0 = make_float4(acc[i][0] + bv[0], acc[i][1] + bv[1],
                                acc[i][2] + bv[2], acc[i][3] + bv[3]);
        float4 c1 = make_float4(acc[i][4] + bv[4], acc[i][5] + bv[5],
                                acc[i][6] + bv[6], acc[i][7] + bv[7]);
        *(float4*)(crow) = c0;
        *(float4*)(crow + 4) = c1;
    }
}

// ---------------------------------------------------------------------------
// Fused attention: per CTA = 16 query rows of one (b,h).
// Full 16x2048 exp(score) row block in smem -> single-pass softmax,
// normalized weights written straight to d_out, AV from smem.
// ---------------------------------------------------------------------------
#define ATTN_SMEM_FLOATS (16*64 + 16*2048 + 64*68 + 16)
#define ATTN_SMEM_BYTES  (ATTN_SMEM_FLOATS * 4)

__global__ void __launch_bounds__(256) attn_kernel(
    const float* __restrict__ qkv,
    float* __restrict__ attnw,     // [B,H,S,S]
    float* __restrict__ attn_out)  // [B,S,E]
{
    extern __shared__ __align__(16) float smem[];
    float* qs   = smem;                 // [16][64] (pre-scaled)
    float* sc   = qs + 16 * 64;         // [16][2048] exp(scores)
    float* kt   = sc + 16 * 2048;       // [64][68] k/v tile (padded)
    float* rinv = kt + 64 * 68;         // [16] 1/rowsum

    const int tid = threadIdx.x;
    const int b = blockIdx.z, h = blockIdx.y;
    const int q0 = blockIdx.x * 16;

    // load q tile, pre-scaled
    {
        int r = tid >> 4;            // 0..15
        int c = (tid & 15) * 4;      // 0..60
        const float* p = qkv + (size_t)(b * SS + q0 + r) * F3 + h * HD + c;
        float4 v = *(const float4*)p;
        qs[r * 64 + c + 0] = v.x * QK_SCALE;
        qs[r * 64 + c + 1] = v.y * QK_SCALE;
        qs[r * 64 + c + 2] = v.z * QK_SCALE;
        qs[r * 64 + c + 3] = v.w * QK_SCALE;
    }
    __syncthreads();

    const int q  = tid >> 4;         // 0..15 query row owned in compute phases
    const int jb = (tid & 15) * 4;   // 4-key / 4-dim group

    // ---- scores: sc[q][j] = exp(q . k_j) ----
    for (int j0 = 0; j0 < SS; j0 += 64) {
#pragma unroll
        for (int l = 0; l < 4; l++) {
            int i = tid + 256 * l;
            int r = i >> 4;
            int c = (i & 15) * 4;
            float4 kv = *(const float4*)(qkv + (size_t)(b * SS + j0 + r) * F3 + EE + h * HD + c);
            float* dst = kt + r * 68 + c;
            dst[0] = kv.x; dst[1] = kv.y; dst[2] = kv.z; dst[3] = kv.w;
        }
        __syncthreads();

        float a0 = 0.f, a1 = 0.f, a2 = 0.f, a3 = 0.f;
        const float* kr0 = kt + (jb + 0) * 68;
        const float* kr1 = kt + (jb + 1) * 68;
        const float* kr2 = kt + (jb + 2) * 68;
        const float* kr3 = kt + (jb + 3) * 68;
        const float* qrow = qs + q * 64;
#pragma unroll
        for (int d = 0; d < 64; d += 4) {
            float4 q4 = *(const float4*)(qrow + d);
            float4 k0 = *(const float4*)(kr0 + d);
            float4 k1 = *(const float4*)(kr1 + d);
            float4 k2 = *(const float4*)(kr2 + d);
            float4 k3 = *(const float4*)(kr3 + d);
            a0 += q4.x * k0.x + q4.y * k0.y + q4.z * k0.z + q4.w * k0.w;
            a1 += q4.x * k1.x + q4.y * k1.y + q4.z * k1.z + q4.w * k1.w;
            a2 += q4.x * k2.x + q4.y * k2.y + q4.z * k2.z + q4.w * k2.w;
            a3 += q4.x * k3.x + q4.y * k3.y + q4.z * k3.z + q4.w * k3.w;
        }
        float* srow = sc + q * 2048 + j0 + jb;
        srow[0] = __expf(a0);
        srow[1] = __expf(a1);
        srow[2] = __expf(a2);
        srow[3] = __expf(a3);
        __syncthreads();
    }

    // ---- row sums -> rinv ----
    {
        int warp = tid >> 5, lane = tid & 31;
        for (int r = warp; r < 16; r += 8) {
            float s = 0.f;
            const float* row = sc + r * 2048;
            for (int j = lane; j < 2048; j += 32) s += row[j];
#pragma unroll
            for (int o = 16; o > 0; o >>= 1) s += __shfl_xor_sync(0xFFFFFFFFu, s, o);
            if (lane == 0) rinv[r] = 1.f / s;
        }
    }
    __syncthreads();

    // ---- write normalized weights to global ----
    {
        float* wbase = attnw + ((size_t)(b * HH + h) * SS + q0) * SS;
        for (int i = tid; i < 16 * 512; i += 256) {
            int r = i >> 9;
            int c = (i & 511) * 4;
            float inv = rinv[r];
            const float* s = sc + r * 2048 + c;
            float4 w = make_float4(s[0] * inv, s[1] * inv, s[2] * inv, s[3] * inv);
            *(float4*)(wbase + (size_t)r * SS + c) = w;
        }
    }

    // ---- AV: out[q][d] = (sum_j sc[q][j] * v[j][d]) * rinv[q] ----
    float acc0 = 0.f, acc1 = 0.f, acc2 = 0.f, acc3 = 0.f;
    const int d4 = jb;  // 4 dims owned
    for (int j0 = 0; j0 < SS; j0 += 64) {
        __syncthreads();
#pragma unroll
        for (int l = 0; l < 4; l++) {
            int i = tid + 256 * l;
            int r = i >> 4;
            int c = (i & 15) * 4;
            float4 vv = *(const float4*)(qkv + (size_t)(b * SS + j0 + r) * F3 + 2 * EE + h * HD + c);
            float* dst = kt + r * 68 + c;
            dst[0] = vv.x; dst[1] = vv.y; dst[2] = vv.z; dst[3] = vv.w;
        }
        __syncthreads();

        const float* srow = sc + q * 2048 + j0;
#pragma unroll 8
        for (int j = 0; j < 64; j++) {
            float w = srow[j];
            float4 v4 = *(const float4*)(kt + j * 68 + d4);
            acc0 = fmaf(w, v4.x, acc0);
            acc1 = fmaf(w, v4.y, acc1);
            acc2 = fmaf(w, v4.z, acc2);
            acc3 = fmaf(w, v4.w, acc3);
        }
    }
    {
        float inv = rinv[q];
        float4 o = make_float4(acc0 * inv, acc1 * inv, acc2 * inv, acc3 * inv);
        *(float4*)(attn_out + (size_t)(b * SS + q0 + q) * EE + h * HD + d4) = o;
    }
}

// ---------------------------------------------------------------------------
extern "C" void kernel_launch(void* const* d_in, const int* in_sizes, int n_in,
                              void* d_out, int out_size)
{
    const float* query = (const float*)d_in[0];
    // d_in[1] (key), d_in[2] (value) are ignored by the reference module
    const float* in_w  = (const float*)d_in[3];
    const float* in_b  = (const float*)d_in[4];
    const float* out_w = (const float*)d_in[5];
    const float* out_b = (const float*)d_in[6];

    float* out   = (float*)d_out;                    // [B,S,E]
    float* attnw = out + (size_t)NN * EE;            // [B,H,S,S]

    void* p;
    cudaGetSymbolAddress(&p, g_qkv);  float* qkv  = (float*)p;
    cudaGetSymbolAddress(&p, g_attn); float* attn = (float*)p;

    // 1) QKV projection: [4096,3072] = query[4096,1024] * in_w[3072,1024]^T + b
    {
        dim3 grid(F3 / 128, NN / 128);
        sgemm_nt_bias<<<grid, 256>>>(query, in_w, in_b, qkv, NN, F3, EE);
    }

    // 2) fused attention
    {
        cudaFuncSetAttribute(attn_kernel, cudaFuncAttributeMaxDynamicSharedMemorySize,
                             ATTN_SMEM_BYTES);
        dim3 grid(SS / 16, HH, BB);
        attn_kernel<<<grid, 256, ATTN_SMEM_BYTES>>>(qkv, attnw, attn);
    }

    // 3) out projection: out[4096,1024] = attn[4096,1024] * out_w[1024,1024]^T + b
    {
        dim3 grid(EE / 128, NN / 128);
        sgemm_nt_bias<<<grid, 256>>>(attn, out_w, out_b, out, NN, EE, EE);
    }
}

// round 3
// speedup vs baseline: 3.1513x; 3.1513x over previous
#include <cuda_runtime.h>
#include <cuda_bf16.h>
#include <math.h>

#define BB 2
#define SS 2048
#define EE 1024
#define HH 16
#define HD 64
#define NN (BB*SS)       // 4096 tokens
#define F3 (3*EE)        // 3072
#define QK_SCALE 0.125f

typedef __nv_bfloat16 bf16;
typedef unsigned int u32;

// ---------------- scratch (device globals; no runtime allocation) ----------
__device__ bf16 g_xh[(size_t)NN * EE], g_xl[(size_t)NN * EE];   // query split
__device__ bf16 g_wih[(size_t)F3 * EE], g_wil[(size_t)F3 * EE]; // in_proj_w split
__device__ bf16 g_woh[(size_t)EE * EE], g_wol[(size_t)EE * EE]; // out_proj_w split
__device__ bf16 g_qh[(size_t)NN * F3], g_ql[(size_t)NN * F3];   // qkv split (GEMM out)
__device__ bf16 g_ah[(size_t)NN * EE], g_al[(size_t)NN * EE];   // attn out split

// ---------------- helpers --------------------------------------------------
__device__ __forceinline__ void split2(float x, bf16& h, bf16& l) {
    h = __float2bfloat16_rn(x);
    l = __float2bfloat16_rn(x - __bfloat162float(h));
}
__device__ __forceinline__ u32 pack2(bf16 a, bf16 b) {
    unsigned short ua = *(unsigned short*)&a, ub = *(unsigned short*)&b;
    return (u32)ua | ((u32)ub << 16);
}
__device__ __forceinline__ float2 bf2f2(u32 u) {
    __nv_bfloat162 v = *(__nv_bfloat162*)&u;
    return __bfloat1622float2(v);
}
__device__ __forceinline__ void mma_bf16(float* d, const u32* a, u32 b0, u32 b1) {
    asm volatile(
        "mma.sync.aligned.m16n8k16.row.col.f32.bf16.bf16.f32 "
        "{%0,%1,%2,%3},{%4,%5,%6,%7},{%8,%9},{%0,%1,%2,%3};"
        : "+f"(d[0]), "+f"(d[1]), "+f"(d[2]), "+f"(d[3])
        : "r"(a[0]), "r"(a[1]), "r"(a[2]), "r"(a[3]), "r"(b0), "r"(b1));
}
#define CP_ASYNC16(sdst, gsrc) \
    asm volatile("cp.async.cg.shared.global [%0], [%1], 16;" :: "r"(sdst), "l"(gsrc))
#define CP_COMMIT() asm volatile("cp.async.commit_group;")
#define CP_WAIT0()  asm volatile("cp.async.wait_group 0;")

// ---------------- split kernel: fp32 -> (hi, lo) bf16 ----------------------
__global__ void __launch_bounds__(256) split_kernel(
    const float* __restrict__ x, bf16* __restrict__ h, bf16* __restrict__ l)
{
    int i = (blockIdx.x * 256 + threadIdx.x) * 4;
    float4 v = *(const float4*)(x + i);
    bf16 h0, l0, h1, l1, h2, l2, h3, l3;
    split2(v.x, h0, l0); split2(v.y, h1, l1);
    split2(v.z, h2, l2); split2(v.w, h3, l3);
    uint2 hp = make_uint2(pack2(h0, h1), pack2(h2, h3));
    uint2 lp = make_uint2(pack2(l0, l1), pack2(l2, l3));
    *(uint2*)(h + i) = hp;
    *(uint2*)(l + i) = lp;
}

// ---------------- bf16x3 GEMM: C[M,N] = (Ah+Al)[M,K] * (Wh+Wl)[N,K]^T + bias
// BM=BN=128, BK=32, 256 thr (8 warps: 4m x 2n), warp tile 32x64.
// outmode 0: Cf fp32;  outmode 1: split to Ch/Cl bf16.
// ---------------------------------------------------------------------------
#define GEMM_SMEM_BYTES (2 * 4 * 128 * 40 * 2)   // 81920

__global__ void __launch_bounds__(256) gemm_bf16x3(
    const bf16* __restrict__ Ah, const bf16* __restrict__ Al,
    const bf16* __restrict__ Wh, const bf16* __restrict__ Wl,
    const float* __restrict__ bias,
    float* __restrict__ Cf, bf16* __restrict__ Ch, bf16* __restrict__ Cl,
    int M, int Nn, int K, int outmode)
{
    extern __shared__ __align__(16) bf16 sm[];
    const int tid = threadIdx.x;
    const int warp = tid >> 5, lane = tid & 31;
    const int g = lane >> 2, tg = lane & 3;
    const int wm = warp >> 1, wn = warp & 1;
    const int m0 = blockIdx.y * 128, n0 = blockIdx.x * 128;

    const int ldrow = tid >> 2;          // not used; per-matrix mapping below
    (void)ldrow;

    float acc[2][8][4];
#pragma unroll
    for (int mt = 0; mt < 2; mt++)
#pragma unroll
        for (int nt = 0; nt < 8; nt++)
#pragma unroll
            for (int i = 0; i < 4; i++) acc[mt][nt][i] = 0.f;

    // buffer base (bf16 units): buf*20480; Ah +0, Al +5120, Wh +10240, Wl +15360
    auto load_tiles = [&](int buf, int k0) {
        bf16* base = sm + buf * 20480;
        const bf16* gsrc[4] = {Ah, Al, Wh, Wl};
#pragma unroll
        for (int mat = 0; mat < 4; mat++) {
            bf16* sbase = base + mat * 5120;
            const bf16* gb = gsrc[mat];
            int rowbase = (mat < 2) ? m0 : n0;
#pragma unroll
            for (int r = 0; r < 2; r++) {
                int idx = tid + 256 * r;           // 0..511
                int row = idx >> 2, cu = idx & 3;  // 8 bf16 per chunk
                const bf16* gp = gb + (size_t)(rowbase + row) * K + k0 + cu * 8;
                u32 sdst = (u32)__cvta_generic_to_shared(sbase + row * 40 + cu * 8);
                CP_ASYNC16(sdst, gp);
            }
        }
        CP_COMMIT();
    };

    load_tiles(0, 0);
    const int KT = K / 32;
    for (int kt = 0; kt < KT; kt++) {
        CP_WAIT0();
        __syncthreads();
        if (kt + 1 < KT) load_tiles((kt + 1) & 1, (kt + 1) * 32);

        const bf16* base = sm + (kt & 1) * 20480;
        const bf16* sAh = base;
        const bf16* sAl = base + 5120;
        const bf16* sWh = base + 10240;
        const bf16* sWl = base + 15360;

#pragma unroll
        for (int ks = 0; ks < 2; ks++) {
            u32 ah[2][4], al[2][4];
#pragma unroll
            for (int mt = 0; mt < 2; mt++)
#pragma unroll
                for (int i = 0; i < 4; i++) {
                    int row = wm * 32 + mt * 16 + g + (i & 1) * 8;
                    int col = tg * 2 + (i >> 1) * 8 + ks * 16;
                    ah[mt][i] = *(const u32*)(sAh + row * 40 + col);
                    al[mt][i] = *(const u32*)(sAl + row * 40 + col);
                }
#pragma unroll
            for (int nt = 0; nt < 8; nt++) {
                int nr = wn * 64 + nt * 8 + g;
                int c0 = tg * 2 + ks * 16;
                u32 bh0 = *(const u32*)(sWh + nr * 40 + c0);
                u32 bh1 = *(const u32*)(sWh + nr * 40 + c0 + 8);
                u32 bl0 = *(const u32*)(sWl + nr * 40 + c0);
                u32 bl1 = *(const u32*)(sWl + nr * 40 + c0 + 8);
#pragma unroll
                for (int mt = 0; mt < 2; mt++) {
                    mma_bf16(acc[mt][nt], ah[mt], bh0, bh1);
                    mma_bf16(acc[mt][nt], ah[mt], bl0, bl1);
                    mma_bf16(acc[mt][nt], al[mt], bh0, bh1);
                }
            }
        }
        __syncthreads();
    }

    // epilogue
#pragma unroll
    for (int mt = 0; mt < 2; mt++) {
#pragma unroll
        for (int nt = 0; nt < 8; nt++) {
            int r0 = m0 + wm * 32 + mt * 16 + g;
            int c0 = n0 + wn * 64 + nt * 8 + tg * 2;
            float b0 = bias[c0], b1 = bias[c0 + 1];
            float v00 = acc[mt][nt][0] + b0, v01 = acc[mt][nt][1] + b1;
            float v10 = acc[mt][nt][2] + b0, v11 = acc[mt][nt][3] + b1;
            if (outmode == 0) {
                *(float2*)(Cf + (size_t)r0 * Nn + c0)       = make_float2(v00, v01);
                *(float2*)(Cf + (size_t)(r0 + 8) * Nn + c0) = make_float2(v10, v11);
            } else {
                bf16 h0, l0, h1, l1;
                split2(v00, h0, l0); split2(v01, h1, l1);
                *(u32*)(Ch + (size_t)r0 * Nn + c0) = pack2(h0, h1);
                *(u32*)(Cl + (size_t)r0 * Nn + c0) = pack2(l0, l1);
                split2(v10, h0, l0); split2(v11, h1, l1);
                *(u32*)(Ch + (size_t)(r0 + 8) * Nn + c0) = pack2(h0, h1);
                *(u32*)(Cl + (size_t)(r0 + 8) * Nn + c0) = pack2(l0, l1);
            }
        }
    }
}

// ---------------- fused attention ------------------------------------------
// Per CTA: 16 q rows of one (b,h). 256 thr = 8 warps.
// smem (bytes): qh 2304 | ql 2304 | sch 65792 | scl 65792 | kth 18432 | ktl 18432 | rinv 64
#define AT_QH   0
#define AT_QL   2304
#define AT_SCH  4608
#define AT_SCL  70400
#define AT_KTH  136192
#define AT_KTL  154624
#define AT_RINV 173056
#define AT_SMEM_BYTES 173120
#define SCS 2056   // sc row stride (bf16)

__global__ void __launch_bounds__(256) attn_kernel(
    const bf16* __restrict__ qh_g, const bf16* __restrict__ ql_g,
    float* __restrict__ attnw,
    bf16* __restrict__ oh_g, bf16* __restrict__ ol_g)
{
    extern __shared__ __align__(16) char smraw[];
    bf16* qh  = (bf16*)(smraw + AT_QH);
    bf16* ql  = (bf16*)(smraw + AT_QL);
    bf16* sch = (bf16*)(smraw + AT_SCH);
    bf16* scl = (bf16*)(smraw + AT_SCL);
    bf16* kth = (bf16*)(smraw + AT_KTH);
    bf16* ktl = (bf16*)(smraw + AT_KTL);
    float* rinv = (float*)(smraw + AT_RINV);

    const int tid = threadIdx.x;
    const int warp = tid >> 5, lane = tid & 31;
    const int g = lane >> 2, tg = lane & 3;
    const int b = blockIdx.z, h = blockIdx.y;
    const int q0 = blockIdx.x * 16;
    const int tokq = b * SS + q0;

    // ---- load Q tile (16x64, hi+lo) ----
    {
        int u = tid & 127;
        int r = u >> 3, cu = u & 7;
        const bf16* src = (tid < 128 ? qh_g : ql_g);
        bf16* dst = (tid < 128 ? qh : ql);
        uint4 v = *(const uint4*)(src + (size_t)(tokq + r) * F3 + h * HD + cu * 8);
        *(uint4*)(dst + r * 72 + cu * 8) = v;
    }

    // ---- phase 1: scores + exp -> sc (hi/lo bf16) ----
    for (int j0 = 0; j0 < SS; j0 += 128) {
        __syncthreads();
        // load K tile 128x64 hi+lo
        int tok0 = b * SS + j0;
        int colb = EE + h * HD;
#pragma unroll
        for (int r = 0; r < 4; r++) {
            int i = tid + 256 * r;
            int row = i >> 3, cu = i & 7;
            *(uint4*)(kth + row * 72 + cu * 8) =
                *(const uint4*)(qh_g + (size_t)(tok0 + row) * F3 + colb + cu * 8);
            *(uint4*)(ktl + row * 72 + cu * 8) =
                *(const uint4*)(ql_g + (size_t)(tok0 + row) * F3 + colb + cu * 8);
        }
        __syncthreads();

        float acc[2][4];
#pragma unroll
        for (int nt = 0; nt < 2; nt++)
#pragma unroll
            for (int i = 0; i < 4; i++) acc[nt][i] = 0.f;

#pragma unroll
        for (int ks = 0; ks < 4; ks++) {
            u32 ah[4], al[4];
#pragma unroll
            for (int i = 0; i < 4; i++) {
                int row = g + (i & 1) * 8;
                int col = tg * 2 + (i >> 1) * 8 + ks * 16;
                ah[i] = *(const u32*)(qh + row * 72 + col);
                al[i] = *(const u32*)(ql + row * 72 + col);
            }
#pragma unroll
            for (int nt = 0; nt < 2; nt++) {
                int nr = warp * 16 + nt * 8 + g;
                int c0 = tg * 2 + ks * 16;
                u32 bh0 = *(const u32*)(kth + nr * 72 + c0);
                u32 bh1 = *(const u32*)(kth + nr * 72 + c0 + 8);
                u32 bl0 = *(const u32*)(ktl + nr * 72 + c0);
                u32 bl1 = *(const u32*)(ktl + nr * 72 + c0 + 8);
                mma_bf16(acc[nt], ah, bh0, bh1);
                mma_bf16(acc[nt], ah, bl0, bl1);
                mma_bf16(acc[nt], al, bh0, bh1);
            }
        }
        // exp + split-store
#pragma unroll
        for (int nt = 0; nt < 2; nt++) {
            int colb2 = j0 + warp * 16 + nt * 8 + tg * 2;
#pragma unroll
            for (int half = 0; half < 2; half++) {
                int row = g + half * 8;
                float e0 = __expf(acc[nt][half * 2 + 0] * QK_SCALE);
                float e1 = __expf(acc[nt][half * 2 + 1] * QK_SCALE);
                bf16 h0, l0, h1, l1;
                split2(e0, h0, l0); split2(e1, h1, l1);
                *(u32*)(sch + row * SCS + colb2) = pack2(h0, h1);
                *(u32*)(scl + row * SCS + colb2) = pack2(l0, l1);
            }
        }
    }
    __syncthreads();

    // ---- phase 2: row sums -> rinv ----
    for (int r = warp; r < 16; r += 8) {
        float s = 0.f;
        for (int j = lane * 4; j < SS; j += 128) {
            uint2 hv = *(const uint2*)(sch + r * SCS + j);
            uint2 lv = *(const uint2*)(scl + r * SCS + j);
            float2 a = bf2f2(hv.x), bq = bf2f2(hv.y);
            float2 c = bf2f2(lv.x), d = bf2f2(lv.y);
            s += (a.x + c.x) + (a.y + c.y) + (bq.x + d.x) + (bq.y + d.y);
        }
#pragma unroll
        for (int o = 16; o > 0; o >>= 1) s += __shfl_xor_sync(0xFFFFFFFFu, s, o);
        if (lane == 0) rinv[r] = 1.f / s;
    }
    __syncthreads();

    // ---- phase 3: write normalized weights ----
    {
        float* wbase = attnw + ((size_t)(b * HH + h) * SS + q0) * SS;
        for (int i = tid; i < 16 * 512; i += 256) {
            int r = i >> 9;
            int c = (i & 511) * 4;
            uint2 hv = *(const uint2*)(sch + r * SCS + c);
            uint2 lv = *(const uint2*)(scl + r * SCS + c);
            float2 a = bf2f2(hv.x), bq = bf2f2(hv.y);
            float2 cc = bf2f2(lv.x), d = bf2f2(lv.y);
            float inv = rinv[r];
            float4 w = make_float4((a.x + cc.x) * inv, (a.y + cc.y) * inv,
                                   (bq.x + d.x) * inv, (bq.y + d.y) * inv);
            *(float4*)(wbase + (size_t)r * SS + c) = w;
        }
    }

    // ---- phase 4: AV ----
    float acc[4] = {0.f, 0.f, 0.f, 0.f};
    const int n0 = warp * 8;
    for (int j0 = 0; j0 < SS; j0 += 128) {
        __syncthreads();
        int tok0 = b * SS + j0;
        int colb = 2 * EE + h * HD;
#pragma unroll
        for (int r = 0; r < 4; r++) {
            int i = tid + 256 * r;
            int row = i >> 3, cu = i & 7;
            *(uint4*)(kth + row * 72 + cu * 8) =
                *(const uint4*)(qh_g + (size_t)(tok0 + row) * F3 + colb + cu * 8);
            *(uint4*)(ktl + row * 72 + cu * 8) =
                *(const uint4*)(ql_g + (size_t)(tok0 + row) * F3 + colb + cu * 8);
        }
        __syncthreads();

#pragma unroll
        for (int ks = 0; ks < 8; ks++) {
            int kk = j0 + ks * 16;
            u32 ah[4], al[4];
#pragma unroll
            for (int i = 0; i < 4; i++) {
                int row = g + (i & 1) * 8;
                int col = kk + tg * 2 + (i >> 1) * 8;
                ah[i] = *(const u32*)(sch + row * SCS + col);
                al[i] = *(const u32*)(scl + row * SCS + col);
            }
            int k0 = ks * 16 + tg * 2;
            int nc = n0 + g;
            u32 bh0 = pack2(kth[k0 * 72 + nc],       kth[(k0 + 1) * 72 + nc]);
            u32 bh1 = pack2(kth[(k0 + 8) * 72 + nc], kth[(k0 + 9) * 72 + nc]);
            u32 bl0 = pack2(ktl[k0 * 72 + nc],       ktl[(k0 + 1) * 72 + nc]);
            u32 bl1 = pack2(ktl[(k0 + 8) * 72 + nc], ktl[(k0 + 9) * 72 + nc]);
            mma_bf16(acc, ah, bh0, bh1);
            mma_bf16(acc, ah, bl0, bl1);
            mma_bf16(acc, al, bh0, bh1);
        }
    }

    // epilogue: normalize, split, store
    {
        int c0 = h * HD + n0 + tg * 2;
        float inv0 = rinv[g], inv1 = rinv[g + 8];
        bf16 h0, l0, h1, l1;
        split2(acc[0] * inv0, h0, l0); split2(acc[1] * inv0, h1, l1);
        *(u32*)(oh_g + (size_t)(tokq + g) * EE + c0) = pack2(h0, h1);
        *(u32*)(ol_g + (size_t)(tokq + g) * EE + c0) = pack2(l0, l1);
        split2(acc[2] * inv1, h0, l0); split2(acc[3] * inv1, h1, l1);
        *(u32*)(oh_g + (size_t)(tokq + g + 8) * EE + c0) = pack2(h0, h1);
        *(u32*)(ol_g + (size_t)(tokq + g + 8) * EE + c0) = pack2(l0, l1);
    }
}

// ---------------------------------------------------------------------------
extern "C" void kernel_launch(void* const* d_in, const int* in_sizes, int n_in,
                              void* d_out, int out_size)
{
    const float* query = (const float*)d_in[0];
    const float* in_w  = (const float*)d_in[3];
    const float* in_b  = (const float*)d_in[4];
    const float* out_w = (const float*)d_in[5];
    const float* out_b = (const float*)d_in[6];

    float* out   = (float*)d_out;
    float* attnw = out + (size_t)NN * EE;

    void* p;
    bf16 *xh, *xl, *wih, *wil, *woh, *wol, *qh, *ql, *ah, *al;
    cudaGetSymbolAddress(&p, g_xh);  xh  = (bf16*)p;
    cudaGetSymbolAddress(&p, g_xl);  xl  = (bf16*)p;
    cudaGetSymbolAddress(&p, g_wih); wih = (bf16*)p;
    cudaGetSymbolAddress(&p, g_wil); wil = (bf16*)p;
    cudaGetSymbolAddress(&p, g_woh); woh = (bf16*)p;
    cudaGetSymbolAddress(&p, g_wol); wol = (bf16*)p;
    cudaGetSymbolAddress(&p, g_qh);  qh  = (bf16*)p;
    cudaGetSymbolAddress(&p, g_ql);  ql  = (bf16*)p;
    cudaGetSymbolAddress(&p, g_ah);  ah  = (bf16*)p;
    cudaGetSymbolAddress(&p, g_al);  al  = (bf16*)p;

    static int attr_done = 0;
    if (!attr_done) {
        cudaFuncSetAttribute(gemm_bf16x3, cudaFuncAttributeMaxDynamicSharedMemorySize,
                             GEMM_SMEM_BYTES);
        cudaFuncSetAttribute(attn_kernel, cudaFuncAttributeMaxDynamicSharedMemorySize,
                             AT_SMEM_BYTES);
        attr_done = 1;
    }

    // splits
    split_kernel<<<(NN * EE) / 1024, 256>>>(query, xh, xl);
    split_kernel<<<(F3 * EE) / 1024, 256>>>(in_w, wih, wil);
    split_kernel<<<(EE * EE) / 1024, 256>>>(out_w, woh, wol);

    // QKV projection -> bf16 split qkv
    {
        dim3 grid(F3 / 128, NN / 128);
        gemm_bf16x3<<<grid, 256, GEMM_SMEM_BYTES>>>(
            xh, xl, wih, wil, in_b, nullptr, qh, ql, NN, F3, EE, 1);
    }

    // fused attention
    {
        dim3 grid(SS / 16, HH, BB);
        attn_kernel<<<grid, 256, AT_SMEM_BYTES>>>(qh, ql, attnw, ah, al);
    }

    // out projection -> fp32 d_out
    {
        dim3 grid(EE / 128, NN / 128);
        gemm_bf16x3<<<grid, 256, GEMM_SMEM_BYTES>>>(
            ah, al, woh, wol, out_b, out, nullptr, nullptr, NN, EE, EE, 0);
    }
}

// round 4
// speedup vs baseline: 5.3361x; 1.6933x over previous
#include <cuda_runtime.h>
#include <cuda_bf16.h>
#include <math.h>

#define BB 2
#define SS 2048
#define EE 1024
#define HH 16
#define HD 64
#define NN (BB*SS)       // 4096 tokens
#define F3 (3*EE)        // 3072
#define QK_SCALE 0.125f

typedef __nv_bfloat16 bf16;
typedef unsigned int u32;

// ---------------- scratch (device globals; no runtime allocation) ----------
__device__ bf16 g_xh[(size_t)NN * EE], g_xl[(size_t)NN * EE];   // query split
__device__ bf16 g_wih[(size_t)F3 * EE], g_wil[(size_t)F3 * EE]; // in_proj_w split
__device__ bf16 g_woh[(size_t)EE * EE], g_wol[(size_t)EE * EE]; // out_proj_w split
__device__ bf16 g_qh[(size_t)NN * F3], g_ql[(size_t)NN * F3];   // qkv split (GEMM out)
__device__ bf16 g_ah[(size_t)NN * EE], g_al[(size_t)NN * EE];   // attn out split

// ---------------- helpers --------------------------------------------------
__device__ __forceinline__ void split2(float x, bf16& h, bf16& l) {
    h = __float2bfloat16_rn(x);
    l = __float2bfloat16_rn(x - __bfloat162float(h));
}
__device__ __forceinline__ u32 pack2(bf16 a, bf16 b) {
    unsigned short ua = *(unsigned short*)&a, ub = *(unsigned short*)&b;
    return (u32)ua | ((u32)ub << 16);
}
__device__ __forceinline__ float2 bf2f2(u32 u) {
    __nv_bfloat162 v = *(__nv_bfloat162*)&u;
    return __bfloat1622float2(v);
}
__device__ __forceinline__ void mma_bf16(float* d, const u32* a, u32 b0, u32 b1) {
    asm volatile(
        "mma.sync.aligned.m16n8k16.row.col.f32.bf16.bf16.f32 "
        "{%0,%1,%2,%3},{%4,%5,%6,%7},{%8,%9},{%0,%1,%2,%3};"
        : "+f"(d[0]), "+f"(d[1]), "+f"(d[2]), "+f"(d[3])
        : "r"(a[0]), "r"(a[1]), "r"(a[2]), "r"(a[3]), "r"(b0), "r"(b1));
}
__device__ __forceinline__ void ldsm_x4(u32* r, u32 addr) {
    asm volatile("ldmatrix.sync.aligned.m8n8.x4.shared.b16 {%0,%1,%2,%3}, [%4];"
        : "=r"(r[0]), "=r"(r[1]), "=r"(r[2]), "=r"(r[3]) : "r"(addr));
}
__device__ __forceinline__ void ldsm_x2(u32& r0, u32& r1, u32 addr) {
    asm volatile("ldmatrix.sync.aligned.m8n8.x2.shared.b16 {%0,%1}, [%2];"
        : "=r"(r0), "=r"(r1) : "r"(addr));
}
__device__ __forceinline__ void ldsm_x2t(u32& r0, u32& r1, u32 addr) {
    asm volatile("ldmatrix.sync.aligned.m8n8.x2.trans.shared.b16 {%0,%1}, [%2];"
        : "=r"(r0), "=r"(r1) : "r"(addr));
}
#define CP_ASYNC16(sdst, gsrc) \
    asm volatile("cp.async.cg.shared.global [%0], [%1], 16;" :: "r"(sdst), "l"(gsrc))
#define CP_COMMIT() asm volatile("cp.async.commit_group;")
#define CP_WAIT(n)  asm volatile("cp.async.wait_group %0;" :: "n"(n))

// ---------------- split kernel: fp32 -> (hi, lo) bf16 ----------------------
__global__ void __launch_bounds__(256) split_kernel(
    const float* __restrict__ x, bf16* __restrict__ h, bf16* __restrict__ l)
{
    int i = (blockIdx.x * 256 + threadIdx.x) * 4;
    float4 v = *(const float4*)(x + i);
    bf16 h0, l0, h1, l1, h2, l2, h3, l3;
    split2(v.x, h0, l0); split2(v.y, h1, l1);
    split2(v.z, h2, l2); split2(v.w, h3, l3);
    *(uint2*)(h + i) = make_uint2(pack2(h0, h1), pack2(h2, h3));
    *(uint2*)(l + i) = make_uint2(pack2(l0, l1), pack2(l2, l3));
}

// ---------------- bf16x3 GEMM (unchanged from R3) --------------------------
#define GEMM_SMEM_BYTES (2 * 4 * 128 * 40 * 2)   // 81920

__global__ void __launch_bounds__(256) gemm_bf16x3(
    const bf16* __restrict__ Ah, const bf16* __restrict__ Al,
    const bf16* __restrict__ Wh, const bf16* __restrict__ Wl,
    const float* __restrict__ bias,
    float* __restrict__ Cf, bf16* __restrict__ Ch, bf16* __restrict__ Cl,
    int M, int Nn, int K, int outmode)
{
    extern __shared__ __align__(16) bf16 sm[];
    const int tid = threadIdx.x;
    const int warp = tid >> 5, lane = tid & 31;
    const int g = lane >> 2, tg = lane & 3;
    const int wm = warp >> 1, wn = warp & 1;
    const int m0 = blockIdx.y * 128, n0 = blockIdx.x * 128;

    float acc[2][8][4];
#pragma unroll
    for (int mt = 0; mt < 2; mt++)
#pragma unroll
        for (int nt = 0; nt < 8; nt++)
#pragma unroll
            for (int i = 0; i < 4; i++) acc[mt][nt][i] = 0.f;

    auto load_tiles = [&](int buf, int k0) {
        bf16* base = sm + buf * 20480;
        const bf16* gsrc[4] = {Ah, Al, Wh, Wl};
#pragma unroll
        for (int mat = 0; mat < 4; mat++) {
            bf16* sbase = base + mat * 5120;
            const bf16* gb = gsrc[mat];
            int rowbase = (mat < 2) ? m0 : n0;
#pragma unroll
            for (int r = 0; r < 2; r++) {
                int idx = tid + 256 * r;
                int row = idx >> 2, cu = idx & 3;
                const bf16* gp = gb + (size_t)(rowbase + row) * K + k0 + cu * 8;
                u32 sdst = (u32)__cvta_generic_to_shared(sbase + row * 40 + cu * 8);
                CP_ASYNC16(sdst, gp);
            }
        }
        CP_COMMIT();
    };

    load_tiles(0, 0);
    const int KT = K / 32;
    for (int kt = 0; kt < KT; kt++) {
        CP_WAIT(0);
        __syncthreads();
        if (kt + 1 < KT) load_tiles((kt + 1) & 1, (kt + 1) * 32);

        const bf16* base = sm + (kt & 1) * 20480;
        const bf16* sAh = base;
        const bf16* sAl = base + 5120;
        const bf16* sWh = base + 10240;
        const bf16* sWl = base + 15360;

#pragma unroll
        for (int ks = 0; ks < 2; ks++) {
            u32 ah[2][4], al[2][4];
#pragma unroll
            for (int mt = 0; mt < 2; mt++)
#pragma unroll
                for (int i = 0; i < 4; i++) {
                    int row = wm * 32 + mt * 16 + g + (i & 1) * 8;
                    int col = tg * 2 + (i >> 1) * 8 + ks * 16;
                    ah[mt][i] = *(const u32*)(sAh + row * 40 + col);
                    al[mt][i] = *(const u32*)(sAl + row * 40 + col);
                }
#pragma unroll
            for (int nt = 0; nt < 8; nt++) {
                int nr = wn * 64 + nt * 8 + g;
                int c0 = tg * 2 + ks * 16;
                u32 bh0 = *(const u32*)(sWh + nr * 40 + c0);
                u32 bh1 = *(const u32*)(sWh + nr * 40 + c0 + 8);
                u32 bl0 = *(const u32*)(sWl + nr * 40 + c0);
                u32 bl1 = *(const u32*)(sWl + nr * 40 + c0 + 8);
#pragma unroll
                for (int mt = 0; mt < 2; mt++) {
                    mma_bf16(acc[mt][nt], ah[mt], bh0, bh1);
                    mma_bf16(acc[mt][nt], ah[mt], bl0, bl1);
                    mma_bf16(acc[mt][nt], al[mt], bh0, bh1);
                }
            }
        }
        __syncthreads();
    }

#pragma unroll
    for (int mt = 0; mt < 2; mt++) {
#pragma unroll
        for (int nt = 0; nt < 8; nt++) {
            int r0 = m0 + wm * 32 + mt * 16 + g;
            int c0 = n0 + wn * 64 + nt * 8 + tg * 2;
            float b0 = bias[c0], b1 = bias[c0 + 1];
            float v00 = acc[mt][nt][0] + b0, v01 = acc[mt][nt][1] + b1;
            float v10 = acc[mt][nt][2] + b0, v11 = acc[mt][nt][3] + b1;
            if (outmode == 0) {
                *(float2*)(Cf + (size_t)r0 * Nn + c0)       = make_float2(v00, v01);
                *(float2*)(Cf + (size_t)(r0 + 8) * Nn + c0) = make_float2(v10, v11);
            } else {
                bf16 h0, l0, h1, l1;
                split2(v00, h0, l0); split2(v01, h1, l1);
                *(u32*)(Ch + (size_t)r0 * Nn + c0) = pack2(h0, h1);
                *(u32*)(Cl + (size_t)r0 * Nn + c0) = pack2(l0, l1);
                split2(v10, h0, l0); split2(v11, h1, l1);
                *(u32*)(Ch + (size_t)(r0 + 8) * Nn + c0) = pack2(h0, h1);
                *(u32*)(Cl + (size_t)(r0 + 8) * Nn + c0) = pack2(l0, l1);
            }
        }
    }
}

// ---------------- fused attention v2 ---------------------------------------
// Per CTA: 16 q rows of one (b,h). 512 threads = 16 warps.
// smem layout (bytes):
//   qh 0..2304 | ql 2304..4608 | sch 4608 (+65792) | scl 70400 (+65792)
//   kth 136192 (2 bufs x 18432) | ktl 173056 (2 bufs) | rinv 209920 (64)
#define AT_QH   0
#define AT_QL   2304
#define AT_SCH  4608
#define AT_SCL  70400
#define AT_KTH  136192
#define AT_KTL  173056
#define AT_RINV 209920
#define AT_SMEM_BYTES 209984
#define SCS 2056       // score row stride (bf16 elems)
#define KTSTR 72       // kv tile row stride (bf16 elems)
#define KT_BUF (128 * KTSTR)
#define NT (SS / 128)  // 16 j-tiles

__global__ void __launch_bounds__(512) attn_kernel(
    const bf16* __restrict__ qh_g, const bf16* __restrict__ ql_g,
    float* __restrict__ attnw,
    bf16* __restrict__ oh_g, bf16* __restrict__ ol_g)
{
    extern __shared__ __align__(16) char smraw[];
    bf16* qh  = (bf16*)(smraw + AT_QH);
    bf16* ql  = (bf16*)(smraw + AT_QL);
    bf16* sch = (bf16*)(smraw + AT_SCH);
    bf16* scl = (bf16*)(smraw + AT_SCL);
    bf16* kth = (bf16*)(smraw + AT_KTH);
    bf16* ktl = (bf16*)(smraw + AT_KTL);
    float* rinv = (float*)(smraw + AT_RINV);

    const int tid = threadIdx.x;
    const int warp = tid >> 5, lane = tid & 31;
    const int g = lane >> 2, tg = lane & 3;
    const int b = blockIdx.z, h = blockIdx.y;
    const int q0 = blockIdx.x * 16;
    const int tokq = b * SS + q0;

    const u32 s_qh  = (u32)__cvta_generic_to_shared(qh);
    const u32 s_ql  = (u32)__cvta_generic_to_shared(ql);
    const u32 s_sch = (u32)__cvta_generic_to_shared(sch);
    const u32 s_scl = (u32)__cvta_generic_to_shared(scl);
    const u32 s_kth = (u32)__cvta_generic_to_shared(kth);
    const u32 s_ktl = (u32)__cvta_generic_to_shared(ktl);

    // cp.async loader for one 128x64 K or V tile (hi+lo)
    auto load_tile = [&](int buf, int tok0, int colb) {
#pragma unroll
        for (int r = 0; r < 4; r++) {
            int i = tid + 512 * r;          // 0..2047
            int mat = i >> 10;              // 0 hi, 1 lo
            int idx = i & 1023;
            int row = idx >> 3, cu = idx & 7;
            const bf16* gp = (mat ? ql_g : qh_g) +
                             (size_t)(tok0 + row) * F3 + colb + cu * 8;
            u32 sd = (mat ? s_ktl : s_kth) + (buf * KT_BUF + row * KTSTR + cu * 8) * 2;
            CP_ASYNC16(sd, gp);
        }
        CP_COMMIT();
    };

    // ---- load Q tile (16x64 hi+lo) ----
    if (tid < 256) {
        int u = tid & 127;
        int r = u >> 3, cu = u & 7;
        const bf16* src = (tid < 128 ? qh_g : ql_g);
        bf16* dst = (tid < 128 ? qh : ql);
        uint4 v = *(const uint4*)(src + (size_t)(tokq + r) * F3 + h * HD + cu * 8);
        *(uint4*)(dst + r * KTSTR + cu * 8) = v;
    }
    load_tile(0, b * SS, EE + h * HD);   // K tile 0
    __syncthreads();

    // ---- preload Q fragments for all 4 k-steps (held in regs all of phase 1)
    u32 qfh[4][4], qfl[4][4];
    {
        int arow = lane & 15, asel = lane >> 4;
#pragma unroll
        for (int ks = 0; ks < 4; ks++) {
            u32 off = (u32)(arow * KTSTR + ks * 16 + asel * 8) * 2;
            ldsm_x4(qfh[ks], s_qh + off);
            ldsm_x4(qfl[ks], s_ql + off);
        }
    }

    // ================= phase 1: scores + exp =================
    const int n0 = warp * 8;               // this warp's 8 key columns in tile
    for (int jt = 0; jt < NT; jt++) {
        if (jt + 1 < NT) {
            load_tile((jt + 1) & 1, b * SS + (jt + 1) * 128, EE + h * HD);
            CP_WAIT(1);
        } else {
            CP_WAIT(0);
        }
        __syncthreads();

        int buf = jt & 1;
        float acc[4] = {0.f, 0.f, 0.f, 0.f};
        // B address: lanes 0-15 rows n0..n0+7 (x2: lanes 0-7 -> k-lo matrix,
        // 8-15 -> k-hi matrix)
        int brow = n0 + (lane & 7);
        int bsel = (lane >> 3) & 1;
#pragma unroll
        for (int ks = 0; ks < 4; ks++) {
            u32 boff = (u32)(buf * KT_BUF + brow * KTSTR + ks * 16 + bsel * 8) * 2;
            u32 bh0, bh1, bl0, bl1;
            ldsm_x2(bh0, bh1, s_kth + boff);
            ldsm_x2(bl0, bl1, s_ktl + boff);
            mma_bf16(acc, qfh[ks], bh0, bh1);
            mma_bf16(acc, qfh[ks], bl0, bl1);
            mma_bf16(acc, qfl[ks], bh0, bh1);
        }
        // exp + split-store to score smem
        {
            int col = jt * 128 + n0 + tg * 2;
            float e0 = __expf(acc[0] * QK_SCALE);
            float e1 = __expf(acc[1] * QK_SCALE);
            float e2 = __expf(acc[2] * QK_SCALE);
            float e3 = __expf(acc[3] * QK_SCALE);
            bf16 h0, l0, h1, l1;
            split2(e0, h0, l0); split2(e1, h1, l1);
            *(u32*)(sch + g * SCS + col) = pack2(h0, h1);
            *(u32*)(scl + g * SCS + col) = pack2(l0, l1);
            split2(e2, h0, l0); split2(e3, h1, l1);
            *(u32*)(sch + (g + 8) * SCS + col) = pack2(h0, h1);
            *(u32*)(scl + (g + 8) * SCS + col) = pack2(l0, l1);
        }
        __syncthreads();
    }

    // prefetch V tile 0 while we do rowsums + weight writes
    load_tile(0, b * SS, 2 * EE + h * HD);

    // ================= phase 2: row sums =================
    {
        int r = warp;  // one row per warp
        float s = 0.f;
        for (int j = lane * 4; j < SS; j += 128) {
            uint2 hv = *(const uint2*)(sch + r * SCS + j);
            uint2 lv = *(const uint2*)(scl + r * SCS + j);
            float2 a = bf2f2(hv.x), bq = bf2f2(hv.y);
            float2 c = bf2f2(lv.x), d = bf2f2(lv.y);
            s += (a.x + c.x) + (a.y + c.y) + (bq.x + d.x) + (bq.y + d.y);
        }
#pragma unroll
        for (int o = 16; o > 0; o >>= 1) s += __shfl_xor_sync(0xFFFFFFFFu, s, o);
        if (lane == 0) rinv[r] = 1.f / s;
    }
    __syncthreads();

    // ================= phase 3: write normalized weights =================
    {
        float* wbase = attnw + ((size_t)(b * HH + h) * SS + q0) * SS;
        for (int i = tid; i < 16 * 512; i += 512) {
            int r = i >> 9;
            int c = (i & 511) * 4;
            uint2 hv = *(const uint2*)(sch + r * SCS + c);
            uint2 lv = *(const uint2*)(scl + r * SCS + c);
            float2 a = bf2f2(hv.x), bq = bf2f2(hv.y);
            float2 cc = bf2f2(lv.x), d = bf2f2(lv.y);
            float inv = rinv[r];
            *(float4*)(wbase + (size_t)r * SS + c) =
                make_float4((a.x + cc.x) * inv, (a.y + cc.y) * inv,
                            (bq.x + d.x) * inv, (bq.y + d.y) * inv);
        }
    }

    // ================= phase 4: AV =================
    // warp -> (wn = n-dim block of 8, wj = which half of the 8 k-steps)
    const int wn = warp & 7, wj = warp >> 3;
    float acc[4] = {0.f, 0.f, 0.f, 0.f};
    for (int jt = 0; jt < NT; jt++) {
        if (jt + 1 < NT) {
            load_tile((jt + 1) & 1, b * SS + (jt + 1) * 128, 2 * EE + h * HD);
            CP_WAIT(1);
        } else {
            CP_WAIT(0);
        }
        __syncthreads();

        int buf = jt & 1;
        int arow = lane & 15, asel = lane >> 4;
#pragma unroll
        for (int ks = 0; ks < 4; ks++) {
            int kkl = (wj * 4 + ks) * 16;            // k offset within tile
            // A: score fragments (16 x k16)
            u32 aoff = (u32)(arow * SCS + jt * 128 + kkl + asel * 8) * 2;
            u32 ah[4], al[4];
            ldsm_x4(ah, s_sch + aoff);
            ldsm_x4(al, s_scl + aoff);
            // B: V fragments via ldmatrix.trans (rows = tokens, cols = dims)
            u32 boff = (u32)(buf * KT_BUF + (kkl + (lane & 15)) * KTSTR + wn * 8) * 2;
            u32 bh0, bh1, bl0, bl1;
            ldsm_x2t(bh0, bh1, s_kth + boff);
            ldsm_x2t(bl0, bl1, s_ktl + boff);
            mma_bf16(acc, ah, bh0, bh1);
            mma_bf16(acc, ah, bl0, bl1);
            mma_bf16(acc, al, bh0, bh1);
        }
        __syncthreads();
    }

    // reduce the two k-halves (warps 8-15 -> smem, warps 0-7 add)
    float* red = (float*)(smraw + AT_QH);   // reuse q area: 16 x 68 floats
    if (wj == 1) {
        *(float2*)(red + g * 68 + wn * 8 + tg * 2)       = make_float2(acc[0], acc[1]);
        *(float2*)(red + (g + 8) * 68 + wn * 8 + tg * 2) = make_float2(acc[2], acc[3]);
    }
    __syncthreads();
    if (wj == 0) {
        float2 r0 = *(const float2*)(red + g * 68 + wn * 8 + tg * 2);
        float2 r1 = *(const float2*)(red + (g + 8) * 68 + wn * 8 + tg * 2);
        acc[0] += r0.x; acc[1] += r0.y; acc[2] += r1.x; acc[3] += r1.y;

        int c0 = h * HD + wn * 8 + tg * 2;
        float inv0 = rinv[g], inv1 = rinv[g + 8];
        bf16 h0, l0, h1, l1;
        split2(acc[0] * inv0, h0, l0); split2(acc[1] * inv0, h1, l1);
        *(u32*)(oh_g + (size_t)(tokq + g) * EE + c0) = pack2(h0, h1);
        *(u32*)(ol_g + (size_t)(tokq + g) * EE + c0) = pack2(l0, l1);
        split2(acc[2] * inv1, h0, l0); split2(acc[3] * inv1, h1, l1);
        *(u32*)(oh_g + (size_t)(tokq + g + 8) * EE + c0) = pack2(h0, h1);
        *(u32*)(ol_g + (size_t)(tokq + g + 8) * EE + c0) = pack2(l0, l1);
    }
}

// ---------------------------------------------------------------------------
extern "C" void kernel_launch(void* const* d_in, const int* in_sizes, int n_in,
                              void* d_out, int out_size)
{
    const float* query = (const float*)d_in[0];
    const float* in_w  = (const float*)d_in[3];
    const float* in_b  = (const float*)d_in[4];
    const float* out_w = (const float*)d_in[5];
    const float* out_b = (const float*)d_in[6];

    float* out   = (float*)d_out;
    float* attnw = out + (size_t)NN * EE;

    void* p;
    bf16 *xh, *xl, *wih, *wil, *woh, *wol, *qh, *ql, *ah, *al;
    cudaGetSymbolAddress(&p, g_xh);  xh  = (bf16*)p;
    cudaGetSymbolAddress(&p, g_xl);  xl  = (bf16*)p;
    cudaGetSymbolAddress(&p, g_wih); wih = (bf16*)p;
    cudaGetSymbolAddress(&p, g_wil); wil = (bf16*)p;
    cudaGetSymbolAddress(&p, g_woh); woh = (bf16*)p;
    cudaGetSymbolAddress(&p, g_wol); wol = (bf16*)p;
    cudaGetSymbolAddress(&p, g_qh);  qh  = (bf16*)p;
    cudaGetSymbolAddress(&p, g_ql);  ql  = (bf16*)p;
    cudaGetSymbolAddress(&p, g_ah);  ah  = (bf16*)p;
    cudaGetSymbolAddress(&p, g_al);  al  = (bf16*)p;

    static int attr_done = 0;
    if (!attr_done) {
        cudaFuncSetAttribute(gemm_bf16x3, cudaFuncAttributeMaxDynamicSharedMemorySize,
                             GEMM_SMEM_BYTES);
        cudaFuncSetAttribute(attn_kernel, cudaFuncAttributeMaxDynamicSharedMemorySize,
                             AT_SMEM_BYTES);
        attr_done = 1;
    }

    // splits
    split_kernel<<<(NN * EE) / 1024, 256>>>(query, xh, xl);
    split_kernel<<<(F3 * EE) / 1024, 256>>>(in_w, wih, wil);
    split_kernel<<<(EE * EE) / 1024, 256>>>(out_w, woh, wol);

    // QKV projection -> bf16 split qkv
    {
        dim3 grid(F3 / 128, NN / 128);
        gemm_bf16x3<<<grid, 256, GEMM_SMEM_BYTES>>>(
            xh, xl, wih, wil, in_b, nullptr, qh, ql, NN, F3, EE, 1);
    }

    // fused attention
    {
        dim3 grid(SS / 16, HH, BB);
        attn_kernel<<<grid, 512, AT_SMEM_BYTES>>>(qh, ql, attnw, ah, al);
    }

    // out projection -> fp32 d_out
    {
        dim3 grid(EE / 128, NN / 128);
        gemm_bf16x3<<<grid, 256, GEMM_SMEM_BYTES>>>(
            ah, al, woh, wol, out_b, out, nullptr, nullptr, NN, EE, EE, 0);
    }
}

// round 5
// speedup vs baseline: 7.4696x; 1.3998x over previous
#include <cuda_runtime.h>
#include <cuda_bf16.h>
#include <cuda_fp16.h>
#include <math.h>

#define BB 2
#define SS 2048
#define EE 1024
#define HH 16
#define HD 64
#define NN (BB*SS)       // 4096 tokens
#define F3 (3*EE)        // 3072
#define QK_SCALE 0.125f

typedef __nv_bfloat16 bf16;
typedef unsigned int u32;

// ---------------- scratch (device globals; no runtime allocation) ----------
__device__ bf16 g_xh[(size_t)NN * EE], g_xl[(size_t)NN * EE];   // query split
__device__ bf16 g_wih[(size_t)F3 * EE], g_wil[(size_t)F3 * EE]; // in_proj_w split
__device__ bf16 g_woh[(size_t)EE * EE], g_wol[(size_t)EE * EE]; // out_proj_w split
__device__ bf16 g_qh[(size_t)NN * F3], g_ql[(size_t)NN * F3];   // qkv split (GEMM out)
__device__ bf16 g_ah[(size_t)NN * EE], g_al[(size_t)NN * EE];   // attn out split
__device__ __half g_vf[(size_t)NN * EE];                        // V as single fp16

// ---------------- helpers --------------------------------------------------
__device__ __forceinline__ void split2(float x, bf16& h, bf16& l) {
    h = __float2bfloat16_rn(x);
    l = __float2bfloat16_rn(x - __bfloat162float(h));
}
__device__ __forceinline__ u32 pack2(bf16 a, bf16 b) {
    unsigned short ua = *(unsigned short*)&a, ub = *(unsigned short*)&b;
    return (u32)ua | ((u32)ub << 16);
}
__device__ __forceinline__ float2 bf2f2(u32 u) {
    __nv_bfloat162 v = *(__nv_bfloat162*)&u;
    return __bfloat1622float2(v);
}
__device__ __forceinline__ u32 packh2(float a, float b) {
    __half2 h = __floats2half2_rn(a, b);
    return *(u32*)&h;
}
__device__ __forceinline__ float2 h2f2(u32 u) {
    __half2 v = *(__half2*)&u;
    return __half22float2(v);
}
__device__ __forceinline__ void mma_bf16(float* d, const u32* a, u32 b0, u32 b1) {
    asm volatile(
        "mma.sync.aligned.m16n8k16.row.col.f32.bf16.bf16.f32 "
        "{%0,%1,%2,%3},{%4,%5,%6,%7},{%8,%9},{%0,%1,%2,%3};"
        : "+f"(d[0]), "+f"(d[1]), "+f"(d[2]), "+f"(d[3])
        : "r"(a[0]), "r"(a[1]), "r"(a[2]), "r"(a[3]), "r"(b0), "r"(b1));
}
__device__ __forceinline__ void mma_f16(float* d, const u32* a, u32 b0, u32 b1) {
    asm volatile(
        "mma.sync.aligned.m16n8k16.row.col.f32.f16.f16.f32 "
        "{%0,%1,%2,%3},{%4,%5,%6,%7},{%8,%9},{%0,%1,%2,%3};"
        : "+f"(d[0]), "+f"(d[1]), "+f"(d[2]), "+f"(d[3])
        : "r"(a[0]), "r"(a[1]), "r"(a[2]), "r"(a[3]), "r"(b0), "r"(b1));
}
__device__ __forceinline__ void ldsm_x4(u32* r, u32 addr) {
    asm volatile("ldmatrix.sync.aligned.m8n8.x4.shared.b16 {%0,%1,%2,%3}, [%4];"
        : "=r"(r[0]), "=r"(r[1]), "=r"(r[2]), "=r"(r[3]) : "r"(addr));
}
__device__ __forceinline__ void ldsm_x2(u32& r0, u32& r1, u32 addr) {
    asm volatile("ldmatrix.sync.aligned.m8n8.x2.shared.b16 {%0,%1}, [%2];"
        : "=r"(r0), "=r"(r1) : "r"(addr));
}
__device__ __forceinline__ void ldsm_x2t(u32& r0, u32& r1, u32 addr) {
    asm volatile("ldmatrix.sync.aligned.m8n8.x2.trans.shared.b16 {%0,%1}, [%2];"
        : "=r"(r0), "=r"(r1) : "r"(addr));
}
#define CP_ASYNC16(sdst, gsrc) \
    asm volatile("cp.async.cg.shared.global [%0], [%1], 16;" :: "r"(sdst), "l"(gsrc))
#define CP_COMMIT() asm volatile("cp.async.commit_group;")
#define CP_WAIT(n)  asm volatile("cp.async.wait_group %0;" :: "n"(n))

// ---------------- split kernel: fp32 -> (hi, lo) bf16 ----------------------
__global__ void __launch_bounds__(256) split_kernel(
    const float* __restrict__ x, bf16* __restrict__ h, bf16* __restrict__ l)
{
    int i = (blockIdx.x * 256 + threadIdx.x) * 4;
    float4 v = *(const float4*)(x + i);
    bf16 h0, l0, h1, l1, h2, l2, h3, l3;
    split2(v.x, h0, l0); split2(v.y, h1, l1);
    split2(v.z, h2, l2); split2(v.w, h3, l3);
    *(uint2*)(h + i) = make_uint2(pack2(h0, h1), pack2(h2, h3));
    *(uint2*)(l + i) = make_uint2(pack2(l0, l1), pack2(l2, l3));
}

// ---------------- bf16x3 GEMM ----------------------------------------------
// outmode 0: Cf fp32;  outmode 1: split to Ch/Cl bf16, plus fp16 copy of the
// V third (cols >= 2*EE) into Vf.
#define GEMM_SMEM_BYTES (2 * 4 * 128 * 40 * 2)   // 81920

__global__ void __launch_bounds__(256) gemm_bf16x3(
    const bf16* __restrict__ Ah, const bf16* __restrict__ Al,
    const bf16* __restrict__ Wh, const bf16* __restrict__ Wl,
    const float* __restrict__ bias,
    float* __restrict__ Cf, bf16* __restrict__ Ch, bf16* __restrict__ Cl,
    __half* __restrict__ Vf,
    int M, int Nn, int K, int outmode)
{
    extern __shared__ __align__(16) bf16 sm[];
    const int tid = threadIdx.x;
    const int warp = tid >> 5, lane = tid & 31;
    const int g = lane >> 2, tg = lane & 3;
    const int wm = warp >> 1, wn = warp & 1;
    const int m0 = blockIdx.y * 128, n0 = blockIdx.x * 128;

    float acc[2][8][4];
#pragma unroll
    for (int mt = 0; mt < 2; mt++)
#pragma unroll
        for (int nt = 0; nt < 8; nt++)
#pragma unroll
            for (int i = 0; i < 4; i++) acc[mt][nt][i] = 0.f;

    auto load_tiles = [&](int buf, int k0) {
        bf16* base = sm + buf * 20480;
        const bf16* gsrc[4] = {Ah, Al, Wh, Wl};
#pragma unroll
        for (int mat = 0; mat < 4; mat++) {
            bf16* sbase = base + mat * 5120;
            const bf16* gb = gsrc[mat];
            int rowbase = (mat < 2) ? m0 : n0;
#pragma unroll
            for (int r = 0; r < 2; r++) {
                int idx = tid + 256 * r;
                int row = idx >> 2, cu = idx & 3;
                const bf16* gp = gb + (size_t)(rowbase + row) * K + k0 + cu * 8;
                u32 sdst = (u32)__cvta_generic_to_shared(sbase + row * 40 + cu * 8);
                CP_ASYNC16(sdst, gp);
            }
        }
        CP_COMMIT();
    };

    load_tiles(0, 0);
    const int KT = K / 32;
    for (int kt = 0; kt < KT; kt++) {
        CP_WAIT(0);
        __syncthreads();
        if (kt + 1 < KT) load_tiles((kt + 1) & 1, (kt + 1) * 32);

        const bf16* base = sm + (kt & 1) * 20480;
        const bf16* sAh = base;
        const bf16* sAl = base + 5120;
        const bf16* sWh = base + 10240;
        const bf16* sWl = base + 15360;

#pragma unroll
        for (int ks = 0; ks < 2; ks++) {
            u32 ah[2][4], al[2][4];
#pragma unroll
            for (int mt = 0; mt < 2; mt++)
#pragma unroll
                for (int i = 0; i < 4; i++) {
                    int row = wm * 32 + mt * 16 + g + (i & 1) * 8;
                    int col = tg * 2 + (i >> 1) * 8 + ks * 16;
                    ah[mt][i] = *(const u32*)(sAh + row * 40 + col);
                    al[mt][i] = *(const u32*)(sAl + row * 40 + col);
                }
#pragma unroll
            for (int nt = 0; nt < 8; nt++) {
                int nr = wn * 64 + nt * 8 + g;
                int c0 = tg * 2 + ks * 16;
                u32 bh0 = *(const u32*)(sWh + nr * 40 + c0);
                u32 bh1 = *(const u32*)(sWh + nr * 40 + c0 + 8);
                u32 bl0 = *(const u32*)(sWl + nr * 40 + c0);
                u32 bl1 = *(const u32*)(sWl + nr * 40 + c0 + 8);
#pragma unroll
                for (int mt = 0; mt < 2; mt++) {
                    mma_bf16(acc[mt][nt], ah[mt], bh0, bh1);
                    mma_bf16(acc[mt][nt], ah[mt], bl0, bl1);
                    mma_bf16(acc[mt][nt], al[mt], bh0, bh1);
                }
            }
        }
        __syncthreads();
    }

#pragma unroll
    for (int mt = 0; mt < 2; mt++) {
#pragma unroll
        for (int nt = 0; nt < 8; nt++) {
            int r0 = m0 + wm * 32 + mt * 16 + g;
            int c0 = n0 + wn * 64 + nt * 8 + tg * 2;
            float b0 = bias[c0], b1 = bias[c0 + 1];
            float v00 = acc[mt][nt][0] + b0, v01 = acc[mt][nt][1] + b1;
            float v10 = acc[mt][nt][2] + b0, v11 = acc[mt][nt][3] + b1;
            if (outmode == 0) {
                *(float2*)(Cf + (size_t)r0 * Nn + c0)       = make_float2(v00, v01);
                *(float2*)(Cf + (size_t)(r0 + 8) * Nn + c0) = make_float2(v10, v11);
            } else {
                bf16 h0, l0, h1, l1;
                split2(v00, h0, l0); split2(v01, h1, l1);
                *(u32*)(Ch + (size_t)r0 * Nn + c0) = pack2(h0, h1);
                *(u32*)(Cl + (size_t)r0 * Nn + c0) = pack2(l0, l1);
                split2(v10, h0, l0); split2(v11, h1, l1);
                *(u32*)(Ch + (size_t)(r0 + 8) * Nn + c0) = pack2(h0, h1);
                *(u32*)(Cl + (size_t)(r0 + 8) * Nn + c0) = pack2(l0, l1);
                if (c0 >= 2 * EE) {   // V third: also write single fp16
                    int vc = c0 - 2 * EE;
                    *(u32*)(Vf + (size_t)r0 * EE + vc)       = packh2(v00, v01);
                    *(u32*)(Vf + (size_t)(r0 + 8) * EE + vc) = packh2(v10, v11);
                }
            }
        }
    }
}

// ---------------- fused attention v3 (M=32, fp16 scores, fp16 PV) ----------
// Per CTA: 32 q rows of one (b,h). 512 threads = 16 warps.
// smem (bytes):
//   qh 0 (4608) | ql 4608 (4608) | sc 9216 (131584, fp16, stride 2056)
//   kth 140800 (2 x 18432) | ktl 177664 (2 x 18432; V fp16 reuses kth region)
//   rinv 214528 (128)                                  total 214656
#define AT_QH   0
#define AT_QL   4608
#define AT_SC   9216
#define AT_KTH  140800
#define AT_KTL  177664
#define AT_RINV 214528
#define AT_SMEM_BYTES 214656
#define SCS 2056       // score row stride (fp16 elems)
#define KTSTR 72       // kv tile row stride (elems)
#define KT_BUF (128 * KTSTR)
#define NT (SS / 128)  // 16 j-tiles

__global__ void __launch_bounds__(512) attn_kernel(
    const bf16* __restrict__ qh_g, const bf16* __restrict__ ql_g,
    const __half* __restrict__ vf_g,
    float* __restrict__ attnw,
    bf16* __restrict__ oh_g, bf16* __restrict__ ol_g)
{
    extern __shared__ __align__(16) char smraw[];
    bf16*   qh = (bf16*)(smraw + AT_QH);
    bf16*   ql = (bf16*)(smraw + AT_QL);
    __half* sc = (__half*)(smraw + AT_SC);
    bf16*  kth = (bf16*)(smraw + AT_KTH);
    bf16*  ktl = (bf16*)(smraw + AT_KTL);
    float* rinv = (float*)(smraw + AT_RINV);

    const int tid = threadIdx.x;
    const int warp = tid >> 5, lane = tid & 31;
    const int g = lane >> 2, tg = lane & 3;
    const int b = blockIdx.z, h = blockIdx.y;
    const int q0 = blockIdx.x * 32;
    const int tokq = b * SS + q0;

    const u32 s_qh  = (u32)__cvta_generic_to_shared(qh);
    const u32 s_ql  = (u32)__cvta_generic_to_shared(ql);
    const u32 s_sc  = (u32)__cvta_generic_to_shared(sc);
    const u32 s_kth = (u32)__cvta_generic_to_shared(kth);
    const u32 s_ktl = (u32)__cvta_generic_to_shared(ktl);

    // K tile loader: 128x64 hi+lo bf16
    auto load_k = [&](int buf, int tok0) {
        int colb = EE + h * HD;
#pragma unroll
        for (int r = 0; r < 4; r++) {
            int i = tid + 512 * r;          // 0..2047
            int mat = i >> 10;              // 0 hi, 1 lo
            int idx = i & 1023;
            int row = idx >> 3, cu = idx & 7;
            const bf16* gp = (mat ? ql_g : qh_g) +
                             (size_t)(tok0 + row) * F3 + colb + cu * 8;
            u32 sd = (mat ? s_ktl : s_kth) + (buf * KT_BUF + row * KTSTR + cu * 8) * 2;
            CP_ASYNC16(sd, gp);
        }
        CP_COMMIT();
    };
    // V tile loader: 128x64 single fp16 (into kth region)
    auto load_v = [&](int buf, int tok0) {
        int colb = h * HD;
#pragma unroll
        for (int r = 0; r < 2; r++) {
            int i = tid + 512 * r;          // 0..1023
            int row = i >> 3, cu = i & 7;
            const __half* gp = vf_g + (size_t)(tok0 + row) * EE + colb + cu * 8;
            u32 sd = s_kth + (buf * KT_BUF + row * KTSTR + cu * 8) * 2;
            CP_ASYNC16(sd, gp);
        }
        CP_COMMIT();
    };

    // ---- load Q tile (32x64 hi+lo): exactly 512 16B chunks ----
    {
        int mat = tid >> 8;                 // 0 hi, 1 lo
        int idx = tid & 255;
        int r = idx >> 3, cu = idx & 7;
        const bf16* src = (mat ? ql_g : qh_g);
        bf16* dst = (mat ? ql : qh);
        uint4 v = *(const uint4*)(src + (size_t)(tokq + r) * F3 + h * HD + cu * 8);
        *(uint4*)(dst + r * KTSTR + cu * 8) = v;
    }
    load_k(0, b * SS);   // K tile 0
    __syncthreads();

    // ---- preload Q fragments: 2 m-sets x 4 k-steps, hi+lo (held in regs) ---
    u32 qfh[2][4][4], qfl[2][4][4];
    {
        int arow = lane & 15, asel = lane >> 4;
#pragma unroll
        for (int ms = 0; ms < 2; ms++)
#pragma unroll
            for (int ks = 0; ks < 4; ks++) {
                u32 off = (u32)((ms * 16 + arow) * KTSTR + ks * 16 + asel * 8) * 2;
                ldsm_x4(qfh[ms][ks], s_qh + off);
                ldsm_x4(qfl[ms][ks], s_ql + off);
            }
    }

    // ================= phase 1: scores + exp -> fp16 smem =================
    const int n0 = warp * 8;               // this warp's 8 key columns in tile
    for (int jt = 0; jt < NT; jt++) {
        if (jt + 1 < NT) {
            load_k((jt + 1) & 1, b * SS + (jt + 1) * 128);
            CP_WAIT(1);
        } else {
            CP_WAIT(0);
        }
        __syncthreads();

        int buf = jt & 1;
        float acc[2][4] = {{0.f,0.f,0.f,0.f},{0.f,0.f,0.f,0.f}};
        int brow = n0 + (lane & 7);
        int bsel = (lane >> 3) & 1;
#pragma unroll
        for (int ks = 0; ks < 4; ks++) {
            u32 boff = (u32)(buf * KT_BUF + brow * KTSTR + ks * 16 + bsel * 8) * 2;
            u32 bh0, bh1, bl0, bl1;
            ldsm_x2(bh0, bh1, s_kth + boff);
            ldsm_x2(bl0, bl1, s_ktl + boff);
#pragma unroll
            for (int ms = 0; ms < 2; ms++) {
                mma_bf16(acc[ms], qfh[ms][ks], bh0, bh1);
                mma_bf16(acc[ms], qfh[ms][ks], bl0, bl1);
                mma_bf16(acc[ms], qfl[ms][ks], bh0, bh1);
            }
        }
        {
            int col = jt * 128 + n0 + tg * 2;
#pragma unroll
            for (int ms = 0; ms < 2; ms++) {
                float e0 = __expf(acc[ms][0] * QK_SCALE);
                float e1 = __expf(acc[ms][1] * QK_SCALE);
                float e2 = __expf(acc[ms][2] * QK_SCALE);
                float e3 = __expf(acc[ms][3] * QK_SCALE);
                *(u32*)(sc + (ms * 16 + g) * SCS + col)     = packh2(e0, e1);
                *(u32*)(sc + (ms * 16 + g + 8) * SCS + col) = packh2(e2, e3);
            }
        }
        __syncthreads();
    }

    // prefetch V tile 0 (overlaps rowsum + weight write)
    load_v(0, b * SS);

    // ================= phase 2: row sums =================
    {
#pragma unroll
        for (int half = 0; half < 2; half++) {
            int r = warp + half * 16;
            float s = 0.f;
            for (int j = lane * 4; j < SS; j += 128) {
                uint2 v = *(const uint2*)(sc + r * SCS + j);
                float2 a = h2f2(v.x), c = h2f2(v.y);
                s += (a.x + a.y) + (c.x + c.y);
            }
#pragma unroll
            for (int o = 16; o > 0; o >>= 1) s += __shfl_xor_sync(0xFFFFFFFFu, s, o);
            if (lane == 0) rinv[r] = 1.f / s;
        }
    }
    __syncthreads();

    // ================= phase 3: write normalized weights =================
    {
        float* wbase = attnw + ((size_t)(b * HH + h) * SS + q0) * SS;
        for (int i = tid; i < 32 * 512; i += 512) {
            int r = i >> 9;
            int c = (i & 511) * 4;
            uint2 v = *(const uint2*)(sc + r * SCS + c);
            float2 a = h2f2(v.x), cc = h2f2(v.y);
            float inv = rinv[r];
            *(float4*)(wbase + (size_t)r * SS + c) =
                make_float4(a.x * inv, a.y * inv, cc.x * inv, cc.y * inv);
        }
    }

    // ================= phase 4: PV (fp16 x fp16, single term) =================
    // warp -> (wm: which 16 of the 32 q rows, wn: 8-col block of HD)
    const int wm = warp >> 3, wn = warp & 7;
    float acc[4] = {0.f, 0.f, 0.f, 0.f};
    const int arow = lane & 15, asel = lane >> 4;
    for (int jt = 0; jt < NT; jt++) {
        if (jt + 1 < NT) {
            load_v((jt + 1) & 1, b * SS + (jt + 1) * 128);
            CP_WAIT(1);
        } else {
            CP_WAIT(0);
        }
        __syncthreads();

        int buf = jt & 1;
        __half* vt = (__half*)kth;   // V fp16 lives in kth region
        (void)vt;
#pragma unroll
        for (int ks = 0; ks < 8; ks++) {
            // A: fp16 score fragment (m16 x k16)
            u32 aoff = (u32)((wm * 16 + arow) * SCS + jt * 128 + ks * 16 + asel * 8) * 2;
            u32 af[4];
            ldsm_x4(af, s_sc + aoff);
            // B: V fragment via ldmatrix.trans (rows = tokens, cols = dims)
            u32 boff = (u32)(buf * KT_BUF + (ks * 16 + arow) * KTSTR + wn * 8) * 2;
            u32 b0, b1;
            ldsm_x2t(b0, b1, s_kth + boff);
            mma_f16(acc, af, b0, b1);
        }
        __syncthreads();
    }

    // epilogue: normalize, split to bf16 hi/lo, store (no cross-warp reduce)
    {
        int r0 = wm * 16 + g;
        int c0 = h * HD + wn * 8 + tg * 2;
        float inv0 = rinv[r0], inv1 = rinv[r0 + 8];
        bf16 h0, l0, h1, l1;
        split2(acc[0] * inv0, h0, l0); split2(acc[1] * inv0, h1, l1);
        *(u32*)(oh_g + (size_t)(tokq + r0) * EE + c0) = pack2(h0, h1);
        *(u32*)(ol_g + (size_t)(tokq + r0) * EE + c0) = pack2(l0, l1);
        split2(acc[2] * inv1, h0, l0); split2(acc[3] * inv1, h1, l1);
        *(u32*)(oh_g + (size_t)(tokq + r0 + 8) * EE + c0) = pack2(h0, h1);
        *(u32*)(ol_g + (size_t)(tokq + r0 + 8) * EE + c0) = pack2(l0, l1);
    }
}

// ---------------------------------------------------------------------------
extern "C" void kernel_launch(void* const* d_in, const int* in_sizes, int n_in,
                              void* d_out, int out_size)
{
    const float* query = (const float*)d_in[0];
    const float* in_w  = (const float*)d_in[3];
    const float* in_b  = (const float*)d_in[4];
    const float* out_w = (const float*)d_in[5];
    const float* out_b = (const float*)d_in[6];

    float* out   = (float*)d_out;
    float* attnw = out + (size_t)NN * EE;

    void* p;
    bf16 *xh, *xl, *wih, *wil, *woh, *wol, *qh, *ql, *ah, *al;
    __half* vf;
    cudaGetSymbolAddress(&p, g_xh);  xh  = (bf16*)p;
    cudaGetSymbolAddress(&p, g_xl);  xl  = (bf16*)p;
    cudaGetSymbolAddress(&p, g_wih); wih = (bf16*)p;
    cudaGetSymbolAddress(&p, g_wil); wil = (bf16*)p;
    cudaGetSymbolAddress(&p, g_woh); woh = (bf16*)p;
    cudaGetSymbolAddress(&p, g_wol); wol = (bf16*)p;
    cudaGetSymbolAddress(&p, g_qh);  qh  = (bf16*)p;
    cudaGetSymbolAddress(&p, g_ql);  ql  = (bf16*)p;
    cudaGetSymbolAddress(&p, g_ah);  ah  = (bf16*)p;
    cudaGetSymbolAddress(&p, g_al);  al  = (bf16*)p;
    cudaGetSymbolAddress(&p, g_vf);  vf  = (__half*)p;

    static int attr_done = 0;
    if (!attr_done) {
        cudaFuncSetAttribute(gemm_bf16x3, cudaFuncAttributeMaxDynamicSharedMemorySize,
                             GEMM_SMEM_BYTES);
        cudaFuncSetAttribute(attn_kernel, cudaFuncAttributeMaxDynamicSharedMemorySize,
                             AT_SMEM_BYTES);
        attr_done = 1;
    }

    // splits
    split_kernel<<<(NN * EE) / 1024, 256>>>(query, xh, xl);
    split_kernel<<<(F3 * EE) / 1024, 256>>>(in_w, wih, wil);
    split_kernel<<<(EE * EE) / 1024, 256>>>(out_w, woh, wol);

    // QKV projection -> bf16 split qkv (+ fp16 V copy)
    {
        dim3 grid(F3 / 128, NN / 128);
        gemm_bf16x3<<<grid, 256, GEMM_SMEM_BYTES>>>(
            xh, xl, wih, wil, in_b, nullptr, qh, ql, vf, NN, F3, EE, 1);
    }

    // fused attention
    {
        dim3 grid(SS / 32, HH, BB);
        attn_kernel<<<grid, 512, AT_SMEM_BYTES>>>(qh, ql, vf, attnw, ah, al);
    }

    // out projection -> fp32 d_out
    {
        dim3 grid(EE / 128, NN / 128);
        gemm_bf16x3<<<grid, 256, GEMM_SMEM_BYTES>>>(
            ah, al, woh, wol, out_b, out, nullptr, nullptr, nullptr, NN, EE, EE, 0);
    }
}

// round 6
// speedup vs baseline: 8.1522x; 1.0914x over previous
#include <cuda_runtime.h>
#include <cuda_bf16.h>
#include <cuda_fp16.h>
#include <math.h>

#define BB 2
#define SS 2048
#define EE 1024
#define HH 16
#define HD 64
#define NN (BB*SS)       // 4096 tokens
#define F3 (3*EE)        // 3072
#define QK_SCALE 0.125f

typedef __nv_bfloat16 bf16;
typedef unsigned int u32;

// ---------------- scratch (device globals; no runtime allocation) ----------
__device__ bf16 g_xh[(size_t)NN * EE], g_xl[(size_t)NN * EE];   // query split
__device__ bf16 g_wih[(size_t)F3 * EE], g_wil[(size_t)F3 * EE]; // in_proj_w split
__device__ bf16 g_woh[(size_t)EE * EE], g_wol[(size_t)EE * EE]; // out_proj_w split
__device__ bf16 g_qh[(size_t)NN * F3], g_ql[(size_t)NN * F3];   // qkv split (GEMM out)
__device__ bf16 g_ah[(size_t)NN * EE], g_al[(size_t)NN * EE];   // attn out split
__device__ __half g_vf[(size_t)NN * EE];                        // V as single fp16

// ---------------- helpers --------------------------------------------------
__device__ __forceinline__ void split2(float x, bf16& h, bf16& l) {
    h = __float2bfloat16_rn(x);
    l = __float2bfloat16_rn(x - __bfloat162float(h));
}
__device__ __forceinline__ u32 pack2(bf16 a, bf16 b) {
    unsigned short ua = *(unsigned short*)&a, ub = *(unsigned short*)&b;
    return (u32)ua | ((u32)ub << 16);
}
__device__ __forceinline__ float2 bf2f2(u32 u) {
    __nv_bfloat162 v = *(__nv_bfloat162*)&u;
    return __bfloat1622float2(v);
}
__device__ __forceinline__ u32 packh2(float a, float b) {
    __half2 h = __floats2half2_rn(a, b);
    return *(u32*)&h;
}
__device__ __forceinline__ float2 h2f2(u32 u) {
    __half2 v = *(__half2*)&u;
    return __half22float2(v);
}
__device__ __forceinline__ void mma_bf16(float* d, const u32* a, u32 b0, u32 b1) {
    asm volatile(
        "mma.sync.aligned.m16n8k16.row.col.f32.bf16.bf16.f32 "
        "{%0,%1,%2,%3},{%4,%5,%6,%7},{%8,%9},{%0,%1,%2,%3};"
        : "+f"(d[0]), "+f"(d[1]), "+f"(d[2]), "+f"(d[3])
        : "r"(a[0]), "r"(a[1]), "r"(a[2]), "r"(a[3]), "r"(b0), "r"(b1));
}
__device__ __forceinline__ void mma_f16(float* d, const u32* a, u32 b0, u32 b1) {
    asm volatile(
        "mma.sync.aligned.m16n8k16.row.col.f32.f16.f16.f32 "
        "{%0,%1,%2,%3},{%4,%5,%6,%7},{%8,%9},{%0,%1,%2,%3};"
        : "+f"(d[0]), "+f"(d[1]), "+f"(d[2]), "+f"(d[3])
        : "r"(a[0]), "r"(a[1]), "r"(a[2]), "r"(a[3]), "r"(b0), "r"(b1));
}
__device__ __forceinline__ void ldsm_x4(u32* r, u32 addr) {
    asm volatile("ldmatrix.sync.aligned.m8n8.x4.shared.b16 {%0,%1,%2,%3}, [%4];"
        : "=r"(r[0]), "=r"(r[1]), "=r"(r[2]), "=r"(r[3]) : "r"(addr));
}
__device__ __forceinline__ void ldsm_x2(u32& r0, u32& r1, u32 addr) {
    asm volatile("ldmatrix.sync.aligned.m8n8.x2.shared.b16 {%0,%1}, [%2];"
        : "=r"(r0), "=r"(r1) : "r"(addr));
}
__device__ __forceinline__ void ldsm_x2t(u32& r0, u32& r1, u32 addr) {
    asm volatile("ldmatrix.sync.aligned.m8n8.x2.trans.shared.b16 {%0,%1}, [%2];"
        : "=r"(r0), "=r"(r1) : "r"(addr));
}
#define CP_ASYNC16(sdst, gsrc) \
    asm volatile("cp.async.cg.shared.global [%0], [%1], 16;" :: "r"(sdst), "l"(gsrc))
#define CP_COMMIT() asm volatile("cp.async.commit_group;")
#define CP_WAIT(n)  asm volatile("cp.async.wait_group %0;" :: "n"(n))

// ---------------- split kernel: fp32 -> (hi, lo) bf16 ----------------------
__global__ void __launch_bounds__(256) split_kernel(
    const float* __restrict__ x, bf16* __restrict__ h, bf16* __restrict__ l)
{
    int i = (blockIdx.x * 256 + threadIdx.x) * 4;
    float4 v = *(const float4*)(x + i);
    bf16 h0, l0, h1, l1, h2, l2, h3, l3;
    split2(v.x, h0, l0); split2(v.y, h1, l1);
    split2(v.z, h2, l2); split2(v.w, h3, l3);
    *(uint2*)(h + i) = make_uint2(pack2(h0, h1), pack2(h2, h3));
    *(uint2*)(l + i) = make_uint2(pack2(l0, l1), pack2(l2, l3));
}

// ---------------- V third -> single fp16 ------------------------------------
__global__ void __launch_bounds__(256) vconv_kernel(
    const bf16* __restrict__ qh, const bf16* __restrict__ ql,
    __half* __restrict__ vf)
{
    int i = blockIdx.x * 256 + threadIdx.x;      // one per 4 elems
    int t = i >> 8;                              // EE/4 = 256 groups per token
    int c = (i & 255) * 4;
    size_t src = (size_t)t * F3 + 2 * EE + c;
    uint2 hv = *(const uint2*)(qh + src);
    uint2 lv = *(const uint2*)(ql + src);
    float2 h0 = bf2f2(hv.x), h1 = bf2f2(hv.y);
    float2 l0 = bf2f2(lv.x), l1 = bf2f2(lv.y);
    *(uint2*)(vf + (size_t)t * EE + c) =
        make_uint2(packh2(h0.x + l0.x, h0.y + l0.y),
                   packh2(h1.x + l1.x, h1.y + l1.y));
}

// ---------------- bf16x3 GEMM (ldmatrix fragments, 2 CTAs/SM) ---------------
// C[M,N] = (Ah+Al)[M,K] * (Wh+Wl)[N,K]^T + bias
// BM=BN=128, BK=32, 256 thr (8 warps: 4m x 2n), warp tile 32x64.
// outmode 0: Cf fp32;  outmode 1: split to Ch/Cl bf16.
#define GEMM_SMEM_BYTES (2 * 4 * 128 * 40 * 2)   // 81920

__global__ void __launch_bounds__(256, 2) gemm_bf16x3(
    const bf16* __restrict__ Ah, const bf16* __restrict__ Al,
    const bf16* __restrict__ Wh, const bf16* __restrict__ Wl,
    const float* __restrict__ bias,
    float* __restrict__ Cf, bf16* __restrict__ Ch, bf16* __restrict__ Cl,
    int M, int Nn, int K, int outmode)
{
    extern __shared__ __align__(16) bf16 sm[];
    const int tid = threadIdx.x;
    const int warp = tid >> 5, lane = tid & 31;
    const int g = lane >> 2, tg = lane & 3;
    const int wm = warp >> 1, wn = warp & 1;
    const int m0 = blockIdx.y * 128, n0 = blockIdx.x * 128;
    const u32 s0 = (u32)__cvta_generic_to_shared(sm);

    // ldmatrix lane mappings (bytes computed later):
    const int la = lane & 15, ha = lane >> 4;            // A: row, k-half
    const int lb = (lane & 7) + ((lane >> 4) << 3);      // B: row within 16
    const int kb = ((lane >> 3) & 1) * 8;                // B: k-half

    float acc[2][8][4];
#pragma unroll
    for (int mt = 0; mt < 2; mt++)
#pragma unroll
        for (int nt = 0; nt < 8; nt++)
#pragma unroll
            for (int i = 0; i < 4; i++) acc[mt][nt][i] = 0.f;

    auto load_tiles = [&](int buf, int k0) {
        bf16* base = sm + buf * 20480;
        const bf16* gsrc[4] = {Ah, Al, Wh, Wl};
#pragma unroll
        for (int mat = 0; mat < 4; mat++) {
            bf16* sbase = base + mat * 5120;
            const bf16* gb = gsrc[mat];
            int rowbase = (mat < 2) ? m0 : n0;
#pragma unroll
            for (int r = 0; r < 2; r++) {
                int idx = tid + 256 * r;
                int row = idx >> 2, cu = idx & 3;
                const bf16* gp = gb + (size_t)(rowbase + row) * K + k0 + cu * 8;
                u32 sdst = (u32)__cvta_generic_to_shared(sbase + row * 40 + cu * 8);
                CP_ASYNC16(sdst, gp);
            }
        }
        CP_COMMIT();
    };

    load_tiles(0, 0);
    const int KT = K / 32;
    for (int kt = 0; kt < KT; kt++) {
        CP_WAIT(0);
        __syncthreads();
        if (kt + 1 < KT) load_tiles((kt + 1) & 1, (kt + 1) * 32);

        const u32 sb = s0 + (kt & 1) * 40960;   // bytes: buffer base
        // mats (bytes): Ah +0, Al +10240, Wh +20480, Wl +30720

#pragma unroll
        for (int ks = 0; ks < 2; ks++) {
            u32 afh[2][4], afl[2][4];
#pragma unroll
            for (int mt = 0; mt < 2; mt++) {
                u32 ao = sb + (u32)(((wm * 32 + mt * 16 + la) * 40 + ks * 16 + ha * 8) * 2);
                ldsm_x4(afh[mt], ao);
                ldsm_x4(afl[mt], ao + 10240);
            }
#pragma unroll
            for (int p = 0; p < 4; p++) {
                u32 bo = sb + 20480 +
                         (u32)(((wn * 64 + p * 16 + lb) * 40 + ks * 16 + kb) * 2);
                u32 bh4[4], bl4[4];
                ldsm_x4(bh4, bo);
                ldsm_x4(bl4, bo + 10240);
#pragma unroll
                for (int half = 0; half < 2; half++) {
                    int nt = p * 2 + half;
                    u32 bh0 = bh4[half * 2], bh1 = bh4[half * 2 + 1];
                    u32 bl0 = bl4[half * 2], bl1 = bl4[half * 2 + 1];
#pragma unroll
                    for (int mt = 0; mt < 2; mt++) {
                        mma_bf16(acc[mt][nt], afh[mt], bh0, bh1);
                        mma_bf16(acc[mt][nt], afh[mt], bl0, bl1);
                        mma_bf16(acc[mt][nt], afl[mt], bh0, bh1);
                    }
                }
            }
        }
        __syncthreads();
    }

#pragma unroll
    for (int mt = 0; mt < 2; mt++) {
#pragma unroll
        for (int nt = 0; nt < 8; nt++) {
            int r0 = m0 + wm * 32 + mt * 16 + g;
            int c0 = n0 + wn * 64 + nt * 8 + tg * 2;
            float b0 = bias[c0], b1 = bias[c0 + 1];
            float v00 = acc[mt][nt][0] + b0, v01 = acc[mt][nt][1] + b1;
            float v10 = acc[mt][nt][2] + b0, v11 = acc[mt][nt][3] + b1;
            if (outmode == 0) {
                *(float2*)(Cf + (size_t)r0 * Nn + c0)       = make_float2(v00, v01);
                *(float2*)(Cf + (size_t)(r0 + 8) * Nn + c0) = make_float2(v10, v11);
            } else {
                bf16 h0, l0, h1, l1;
                split2(v00, h0, l0); split2(v01, h1, l1);
                *(u32*)(Ch + (size_t)r0 * Nn + c0) = pack2(h0, h1);
                *(u32*)(Cl + (size_t)r0 * Nn + c0) = pack2(l0, l1);
                split2(v10, h0, l0); split2(v11, h1, l1);
                *(u32*)(Ch + (size_t)(r0 + 8) * Nn + c0) = pack2(h0, h1);
                *(u32*)(Cl + (size_t)(r0 + 8) * Nn + c0) = pack2(l0, l1);
            }
        }
    }
}

// ---------------- fused attention (M=32, fp16 scores, fp16 PV) --------------
#define AT_QH   0
#define AT_QL   4608
#define AT_SC   9216
#define AT_KTH  140800
#define AT_KTL  177664
#define AT_RINV 214528
#define AT_SMEM_BYTES 214656
#define SCS 2056       // score row stride (fp16 elems)
#define KTSTR 72       // kv tile row stride (elems)
#define KT_BUF (128 * KTSTR)
#define NT (SS / 128)  // 16 j-tiles

__global__ void __launch_bounds__(512) attn_kernel(
    const bf16* __restrict__ qh_g, const bf16* __restrict__ ql_g,
    const __half* __restrict__ vf_g,
    float* __restrict__ attnw,
    bf16* __restrict__ oh_g, bf16* __restrict__ ol_g)
{
    extern __shared__ __align__(16) char smraw[];
    bf16*   qh = (bf16*)(smraw + AT_QH);
    bf16*   ql = (bf16*)(smraw + AT_QL);
    __half* sc = (__half*)(smraw + AT_SC);
    bf16*  kth = (bf16*)(smraw + AT_KTH);
    bf16*  ktl = (bf16*)(smraw + AT_KTL);
    float* rinv = (float*)(smraw + AT_RINV);

    const int tid = threadIdx.x;
    const int warp = tid >> 5, lane = tid & 31;
    const int g = lane >> 2, tg = lane & 3;
    const int b = blockIdx.z, h = blockIdx.y;
    const int q0 = blockIdx.x * 32;
    const int tokq = b * SS + q0;

    const u32 s_qh  = (u32)__cvta_generic_to_shared(qh);
    const u32 s_ql  = (u32)__cvta_generic_to_shared(ql);
    const u32 s_sc  = (u32)__cvta_generic_to_shared(sc);
    const u32 s_kth = (u32)__cvta_generic_to_shared(kth);
    const u32 s_ktl = (u32)__cvta_generic_to_shared(ktl);

    auto load_k = [&](int buf, int tok0) {
        int colb = EE + h * HD;
#pragma unroll
        for (int r = 0; r < 4; r++) {
            int i = tid + 512 * r;
            int mat = i >> 10;
            int idx = i & 1023;
            int row = idx >> 3, cu = idx & 7;
            const bf16* gp = (mat ? ql_g : qh_g) +
                             (size_t)(tok0 + row) * F3 + colb + cu * 8;
            u32 sd = (mat ? s_ktl : s_kth) + (buf * KT_BUF + row * KTSTR + cu * 8) * 2;
            CP_ASYNC16(sd, gp);
        }
        CP_COMMIT();
    };
    auto load_v = [&](int buf, int tok0) {
        int colb = h * HD;
#pragma unroll
        for (int r = 0; r < 2; r++) {
            int i = tid + 512 * r;
            int row = i >> 3, cu = i & 7;
            const __half* gp = vf_g + (size_t)(tok0 + row) * EE + colb + cu * 8;
            u32 sd = s_kth + (buf * KT_BUF + row * KTSTR + cu * 8) * 2;
            CP_ASYNC16(sd, gp);
        }
        CP_COMMIT();
    };

    // ---- load Q tile (32x64 hi+lo) ----
    {
        int mat = tid >> 8;
        int idx = tid & 255;
        int r = idx >> 3, cu = idx & 7;
        const bf16* src = (mat ? ql_g : qh_g);
        bf16* dst = (mat ? ql : qh);
        uint4 v = *(const uint4*)(src + (size_t)(tokq + r) * F3 + h * HD + cu * 8);
        *(uint4*)(dst + r * KTSTR + cu * 8) = v;
    }
    load_k(0, b * SS);
    __syncthreads();

    // ---- preload Q fragments ----
    u32 qfh[2][4][4], qfl[2][4][4];
    {
        int arow = lane & 15, asel = lane >> 4;
#pragma unroll
        for (int ms = 0; ms < 2; ms++)
#pragma unroll
            for (int ks = 0; ks < 4; ks++) {
                u32 off = (u32)((ms * 16 + arow) * KTSTR + ks * 16 + asel * 8) * 2;
                ldsm_x4(qfh[ms][ks], s_qh + off);
                ldsm_x4(qfl[ms][ks], s_ql + off);
            }
    }

    // ================= phase 1: scores + exp -> fp16 smem =================
    const int n0 = warp * 8;
    for (int jt = 0; jt < NT; jt++) {
        if (jt + 1 < NT) {
            load_k((jt + 1) & 1, b * SS + (jt + 1) * 128);
            CP_WAIT(1);
        } else {
            CP_WAIT(0);
        }
        __syncthreads();

        int buf = jt & 1;
        float acc[2][4] = {{0.f,0.f,0.f,0.f},{0.f,0.f,0.f,0.f}};
        int brow = n0 + (lane & 7);
        int bsel = (lane >> 3) & 1;
#pragma unroll
        for (int ks = 0; ks < 4; ks++) {
            u32 boff = (u32)(buf * KT_BUF + brow * KTSTR + ks * 16 + bsel * 8) * 2;
            u32 bh0, bh1, bl0, bl1;
            ldsm_x2(bh0, bh1, s_kth + boff);
            ldsm_x2(bl0, bl1, s_ktl + boff);
#pragma unroll
            for (int ms = 0; ms < 2; ms++) {
                mma_bf16(acc[ms], qfh[ms][ks], bh0, bh1);
                mma_bf16(acc[ms], qfh[ms][ks], bl0, bl1);
                mma_bf16(acc[ms], qfl[ms][ks], bh0, bh1);
            }
        }
        {
            int col = jt * 128 + n0 + tg * 2;
#pragma unroll
            for (int ms = 0; ms < 2; ms++) {
                float e0 = __expf(acc[ms][0] * QK_SCALE);
                float e1 = __expf(acc[ms][1] * QK_SCALE);
                float e2 = __expf(acc[ms][2] * QK_SCALE);
                float e3 = __expf(acc[ms][3] * QK_SCALE);
                *(u32*)(sc + (ms * 16 + g) * SCS + col)     = packh2(e0, e1);
                *(u32*)(sc + (ms * 16 + g + 8) * SCS + col) = packh2(e2, e3);
            }
        }
        __syncthreads();
    }

    load_v(0, b * SS);

    // ================= phase 2: row sums =================
    {
#pragma unroll
        for (int half = 0; half < 2; half++) {
            int r = warp + half * 16;
            float s = 0.f;
            for (int j = lane * 4; j < SS; j += 128) {
                uint2 v = *(const uint2*)(sc + r * SCS + j);
                float2 a = h2f2(v.x), c = h2f2(v.y);
                s += (a.x + a.y) + (c.x + c.y);
            }
#pragma unroll
            for (int o = 16; o > 0; o >>= 1) s += __shfl_xor_sync(0xFFFFFFFFu, s, o);
            if (lane == 0) rinv[r] = 1.f / s;
        }
    }
    __syncthreads();

    // ================= phase 3: write normalized weights =================
    {
        float* wbase = attnw + ((size_t)(b * HH + h) * SS + q0) * SS;
        for (int i = tid; i < 32 * 512; i += 512) {
            int r = i >> 9;
            int c = (i & 511) * 4;
            uint2 v = *(const uint2*)(sc + r * SCS + c);
            float2 a = h2f2(v.x), cc = h2f2(v.y);
            float inv = rinv[r];
            *(float4*)(wbase + (size_t)r * SS + c) =
                make_float4(a.x * inv, a.y * inv, cc.x * inv, cc.y * inv);
        }
    }

    // ================= phase 4: PV (fp16, single term) =================
    const int wm = warp >> 3, wn = warp & 7;
    float acc[4] = {0.f, 0.f, 0.f, 0.f};
    const int arow = lane & 15, asel = lane >> 4;
    for (int jt = 0; jt < NT; jt++) {
        if (jt + 1 < NT) {
            load_v((jt + 1) & 1, b * SS + (jt + 1) * 128);
            CP_WAIT(1);
        } else {
            CP_WAIT(0);
        }
        __syncthreads();

        int buf = jt & 1;
#pragma unroll
        for (int ks = 0; ks < 8; ks++) {
            u32 aoff = (u32)((wm * 16 + arow) * SCS + jt * 128 + ks * 16 + asel * 8) * 2;
            u32 af[4];
            ldsm_x4(af, s_sc + aoff);
            u32 boff = (u32)(buf * KT_BUF + (ks * 16 + arow) * KTSTR + wn * 8) * 2;
            u32 b0, b1;
            ldsm_x2t(b0, b1, s_kth + boff);
            mma_f16(acc, af, b0, b1);
        }
        __syncthreads();
    }

    {
        int r0 = wm * 16 + g;
        int c0 = h * HD + wn * 8 + tg * 2;
        float inv0 = rinv[r0], inv1 = rinv[r0 + 8];
        bf16 h0, l0, h1, l1;
        split2(acc[0] * inv0, h0, l0); split2(acc[1] * inv0, h1, l1);
        *(u32*)(oh_g + (size_t)(tokq + r0) * EE + c0) = pack2(h0, h1);
        *(u32*)(ol_g + (size_t)(tokq + r0) * EE + c0) = pack2(l0, l1);
        split2(acc[2] * inv1, h0, l0); split2(acc[3] * inv1, h1, l1);
        *(u32*)(oh_g + (size_t)(tokq + r0 + 8) * EE + c0) = pack2(h0, h1);
        *(u32*)(ol_g + (size_t)(tokq + r0 + 8) * EE + c0) = pack2(l0, l1);
    }
}

// ---------------------------------------------------------------------------
extern "C" void kernel_launch(void* const* d_in, const int* in_sizes, int n_in,
                              void* d_out, int out_size)
{
    const float* query = (const float*)d_in[0];
    const float* in_w  = (const float*)d_in[3];
    const float* in_b  = (const float*)d_in[4];
    const float* out_w = (const float*)d_in[5];
    const float* out_b = (const float*)d_in[6];

    float* out   = (float*)d_out;
    float* attnw = out + (size_t)NN * EE;

    void* p;
    bf16 *xh, *xl, *wih, *wil, *woh, *wol, *qh, *ql, *ah, *al;
    __half* vf;
    cudaGetSymbolAddress(&p, g_xh);  xh  = (bf16*)p;
    cudaGetSymbolAddress(&p, g_xl);  xl  = (bf16*)p;
    cudaGetSymbolAddress(&p, g_wih); wih = (bf16*)p;
    cudaGetSymbolAddress(&p, g_wil); wil = (bf16*)p;
    cudaGetSymbolAddress(&p, g_woh); woh = (bf16*)p;
    cudaGetSymbolAddress(&p, g_wol); wol = (bf16*)p;
    cudaGetSymbolAddress(&p, g_qh);  qh  = (bf16*)p;
    cudaGetSymbolAddress(&p, g_ql);  ql  = (bf16*)p;
    cudaGetSymbolAddress(&p, g_ah);  ah  = (bf16*)p;
    cudaGetSymbolAddress(&p, g_al);  al  = (bf16*)p;
    cudaGetSymbolAddress(&p, g_vf);  vf  = (__half*)p;

    static int attr_done = 0;
    if (!attr_done) {
        cudaFuncSetAttribute(gemm_bf16x3, cudaFuncAttributeMaxDynamicSharedMemorySize,
                             GEMM_SMEM_BYTES);
        cudaFuncSetAttribute(attn_kernel, cudaFuncAttributeMaxDynamicSharedMemorySize,
                             AT_SMEM_BYTES);
        attr_done = 1;
    }

    // splits
    split_kernel<<<(NN * EE) / 1024, 256>>>(query, xh, xl);
    split_kernel<<<(F3 * EE) / 1024, 256>>>(in_w, wih, wil);
    split_kernel<<<(EE * EE) / 1024, 256>>>(out_w, woh, wol);

    // QKV projection -> bf16 split qkv
    {
        dim3 grid(F3 / 128, NN / 128);
        gemm_bf16x3<<<grid, 256, GEMM_SMEM_BYTES>>>(
            xh, xl, wih, wil, in_b, nullptr, qh, ql, NN, F3, EE, 1);
    }

    // V third -> single fp16
    vconv_kernel<<<(NN * EE) / 1024, 256>>>(qh, ql, vf);

    // fused attention
    {
        dim3 grid(SS / 32, HH, BB);
        attn_kernel<<<grid, 512, AT_SMEM_BYTES>>>(qh, ql, vf, attnw, ah, al);
    }

    // out projection -> fp32 d_out
    {
        dim3 grid(EE / 128, NN / 128);
        gemm_bf16x3<<<grid, 256, GEMM_SMEM_BYTES>>>(
            ah, al, woh, wol, out_b, out, nullptr, nullptr, NN, EE, EE, 0);
    }
}

// round 7
// speedup vs baseline: 9.5516x; 1.1717x over previous
#include <cuda_runtime.h>
#include <cuda_bf16.h>
#include <cuda_fp16.h>
#include <math.h>

#define BB 2
#define SS 2048
#define EE 1024
#define HH 16
#define HD 64
#define NN (BB*SS)       // 4096 tokens
#define F3 (3*EE)        // 3072
#define QK_SCALE 0.125f

typedef __nv_bfloat16 bf16;
typedef unsigned int u32;

// ---------------- scratch (device globals; no runtime allocation) ----------
__device__ bf16 g_xh[(size_t)NN * EE], g_xl[(size_t)NN * EE];   // query split
__device__ bf16 g_wih[(size_t)F3 * EE], g_wil[(size_t)F3 * EE]; // in_proj_w split
__device__ __half g_wof[(size_t)EE * EE];                       // out_proj_w fp16
__device__ __half g_qkvf[(size_t)NN * F3];                      // qkv fp16
__device__ __half g_af[(size_t)NN * EE];                        // attn out fp16

// ---------------- helpers --------------------------------------------------
__device__ __forceinline__ void split2(float x, bf16& h, bf16& l) {
    h = __float2bfloat16_rn(x);
    l = __float2bfloat16_rn(x - __bfloat162float(h));
}
__device__ __forceinline__ u32 pack2(bf16 a, bf16 b) {
    unsigned short ua = *(unsigned short*)&a, ub = *(unsigned short*)&b;
    return (u32)ua | ((u32)ub << 16);
}
__device__ __forceinline__ u32 packh2(float a, float b) {
    __half2 h = __floats2half2_rn(a, b);
    return *(u32*)&h;
}
__device__ __forceinline__ float2 h2f2(u32 u) {
    __half2 v = *(__half2*)&u;
    return __half22float2(v);
}
__device__ __forceinline__ void mma_bf16(float* d, const u32* a, u32 b0, u32 b1) {
    asm volatile(
        "mma.sync.aligned.m16n8k16.row.col.f32.bf16.bf16.f32 "
        "{%0,%1,%2,%3},{%4,%5,%6,%7},{%8,%9},{%0,%1,%2,%3};"
        : "+f"(d[0]), "+f"(d[1]), "+f"(d[2]), "+f"(d[3])
        : "r"(a[0]), "r"(a[1]), "r"(a[2]), "r"(a[3]), "r"(b0), "r"(b1));
}
__device__ __forceinline__ void mma_f16(float* d, const u32* a, u32 b0, u32 b1) {
    asm volatile(
        "mma.sync.aligned.m16n8k16.row.col.f32.f16.f16.f32 "
        "{%0,%1,%2,%3},{%4,%5,%6,%7},{%8,%9},{%0,%1,%2,%3};"
        : "+f"(d[0]), "+f"(d[1]), "+f"(d[2]), "+f"(d[3])
        : "r"(a[0]), "r"(a[1]), "r"(a[2]), "r"(a[3]), "r"(b0), "r"(b1));
}
__device__ __forceinline__ void ldsm_x4(u32* r, u32 addr) {
    asm volatile("ldmatrix.sync.aligned.m8n8.x4.shared.b16 {%0,%1,%2,%3}, [%4];"
        : "=r"(r[0]), "=r"(r[1]), "=r"(r[2]), "=r"(r[3]) : "r"(addr));
}
__device__ __forceinline__ void ldsm_x2(u32& r0, u32& r1, u32 addr) {
    asm volatile("ldmatrix.sync.aligned.m8n8.x2.shared.b16 {%0,%1}, [%2];"
        : "=r"(r0), "=r"(r1) : "r"(addr));
}
__device__ __forceinline__ void ldsm_x2t(u32& r0, u32& r1, u32 addr) {
    asm volatile("ldmatrix.sync.aligned.m8n8.x2.trans.shared.b16 {%0,%1}, [%2];"
        : "=r"(r0), "=r"(r1) : "r"(addr));
}
#define CP_ASYNC16(sdst, gsrc) \
    asm volatile("cp.async.cg.shared.global [%0], [%1], 16;" :: "r"(sdst), "l"(gsrc))
#define CP_COMMIT() asm volatile("cp.async.commit_group;")
#define CP_WAIT(n)  asm volatile("cp.async.wait_group %0;" :: "n"(n))

// ---------------- split kernel: fp32 -> (hi, lo) bf16 ----------------------
__global__ void __launch_bounds__(256) split_kernel(
    const float* __restrict__ x, bf16* __restrict__ h, bf16* __restrict__ l)
{
    int i = (blockIdx.x * 256 + threadIdx.x) * 4;
    float4 v = *(const float4*)(x + i);
    bf16 h0, l0, h1, l1, h2, l2, h3, l3;
    split2(v.x, h0, l0); split2(v.y, h1, l1);
    split2(v.z, h2, l2); split2(v.w, h3, l3);
    *(uint2*)(h + i) = make_uint2(pack2(h0, h1), pack2(h2, h3));
    *(uint2*)(l + i) = make_uint2(pack2(l0, l1), pack2(l2, l3));
}

// ---------------- fconv: fp32 -> fp16 ---------------------------------------
__global__ void __launch_bounds__(256) fconv_kernel(
    const float* __restrict__ x, __half* __restrict__ y)
{
    int i = (blockIdx.x * 256 + threadIdx.x) * 4;
    float4 v = *(const float4*)(x + i);
    *(uint2*)(y + i) = make_uint2(packh2(v.x, v.y), packh2(v.z, v.w));
}

// ---------------- bf16x3 GEMM -> fp16 output --------------------------------
// C[M,N] = (Ah+Al)[M,K] * (Wh+Wl)[N,K]^T + bias, written as single fp16.
// BM=BN=128, BK=32, 256 thr (8 warps: 4m x 2n), warp tile 32x64.
#define GEMM_SMEM_BYTES (2 * 4 * 128 * 40 * 2)   // 81920

__global__ void __launch_bounds__(256, 2) gemm_bf16x3(
    const bf16* __restrict__ Ah, const bf16* __restrict__ Al,
    const bf16* __restrict__ Wh, const bf16* __restrict__ Wl,
    const float* __restrict__ bias, __half* __restrict__ C,
    int M, int Nn, int K)
{
    extern __shared__ __align__(16) bf16 sm[];
    const int tid = threadIdx.x;
    const int warp = tid >> 5, lane = tid & 31;
    const int g = lane >> 2, tg = lane & 3;
    const int wm = warp >> 1, wn = warp & 1;
    const int m0 = blockIdx.y * 128, n0 = blockIdx.x * 128;
    const u32 s0 = (u32)__cvta_generic_to_shared(sm);

    const int la = lane & 15, ha = lane >> 4;
    const int lb = (lane & 7) + ((lane >> 4) << 3);
    const int kb = ((lane >> 3) & 1) * 8;

    float acc[2][8][4];
#pragma unroll
    for (int mt = 0; mt < 2; mt++)
#pragma unroll
        for (int nt = 0; nt < 8; nt++)
#pragma unroll
            for (int i = 0; i < 4; i++) acc[mt][nt][i] = 0.f;

    auto load_tiles = [&](int buf, int k0) {
        bf16* base = sm + buf * 20480;
        const bf16* gsrc[4] = {Ah, Al, Wh, Wl};
#pragma unroll
        for (int mat = 0; mat < 4; mat++) {
            bf16* sbase = base + mat * 5120;
            const bf16* gb = gsrc[mat];
            int rowbase = (mat < 2) ? m0 : n0;
#pragma unroll
            for (int r = 0; r < 2; r++) {
                int idx = tid + 256 * r;
                int row = idx >> 2, cu = idx & 3;
                const bf16* gp = gb + (size_t)(rowbase + row) * K + k0 + cu * 8;
                u32 sdst = (u32)__cvta_generic_to_shared(sbase + row * 40 + cu * 8);
                CP_ASYNC16(sdst, gp);
            }
        }
        CP_COMMIT();
    };

    load_tiles(0, 0);
    const int KT = K / 32;
    for (int kt = 0; kt < KT; kt++) {
        CP_WAIT(0);
        __syncthreads();
        if (kt + 1 < KT) load_tiles((kt + 1) & 1, (kt + 1) * 32);

        const u32 sb = s0 + (kt & 1) * 40960;   // bytes

#pragma unroll
        for (int ks = 0; ks < 2; ks++) {
            u32 afh[2][4], afl[2][4];
#pragma unroll
            for (int mt = 0; mt < 2; mt++) {
                u32 ao = sb + (u32)(((wm * 32 + mt * 16 + la) * 40 + ks * 16 + ha * 8) * 2);
                ldsm_x4(afh[mt], ao);
                ldsm_x4(afl[mt], ao + 10240);
            }
#pragma unroll
            for (int p = 0; p < 4; p++) {
                u32 bo = sb + 20480 +
                         (u32)(((wn * 64 + p * 16 + lb) * 40 + ks * 16 + kb) * 2);
                u32 bh4[4], bl4[4];
                ldsm_x4(bh4, bo);
                ldsm_x4(bl4, bo + 10240);
#pragma unroll
                for (int half = 0; half < 2; half++) {
                    int nt = p * 2 + half;
                    u32 bh0 = bh4[half * 2], bh1 = bh4[half * 2 + 1];
                    u32 bl0 = bl4[half * 2], bl1 = bl4[half * 2 + 1];
#pragma unroll
                    for (int mt = 0; mt < 2; mt++) {
                        mma_bf16(acc[mt][nt], afh[mt], bh0, bh1);
                        mma_bf16(acc[mt][nt], afh[mt], bl0, bl1);
                        mma_bf16(acc[mt][nt], afl[mt], bh0, bh1);
                    }
                }
            }
        }
        __syncthreads();
    }

#pragma unroll
    for (int mt = 0; mt < 2; mt++) {
#pragma unroll
        for (int nt = 0; nt < 8; nt++) {
            int r0 = m0 + wm * 32 + mt * 16 + g;
            int c0 = n0 + wn * 64 + nt * 8 + tg * 2;
            float b0 = bias[c0], b1 = bias[c0 + 1];
            *(u32*)(C + (size_t)r0 * Nn + c0) =
                packh2(acc[mt][nt][0] + b0, acc[mt][nt][1] + b1);
            *(u32*)(C + (size_t)(r0 + 8) * Nn + c0) =
                packh2(acc[mt][nt][2] + b0, acc[mt][nt][3] + b1);
        }
    }
}

// ---------------- fp16 single-term GEMM -> fp32 output ----------------------
// C[M,N] = A[M,K] * W[N,K]^T + bias
#define GEMMF_SMEM_BYTES (2 * 2 * 128 * 40 * 2)  // 40960

__global__ void __launch_bounds__(256, 2) gemm_f16(
    const __half* __restrict__ A, const __half* __restrict__ W,
    const float* __restrict__ bias, float* __restrict__ Cf,
    int M, int Nn, int K)
{
    extern __shared__ __align__(16) __half smf[];
    const int tid = threadIdx.x;
    const int warp = tid >> 5, lane = tid & 31;
    const int g = lane >> 2, tg = lane & 3;
    const int wm = warp >> 1, wn = warp & 1;
    const int m0 = blockIdx.y * 128, n0 = blockIdx.x * 128;
    const u32 s0 = (u32)__cvta_generic_to_shared(smf);

    const int la = lane & 15, ha = lane >> 4;
    const int lb = (lane & 7) + ((lane >> 4) << 3);
    const int kb = ((lane >> 3) & 1) * 8;

    float acc[2][8][4];
#pragma unroll
    for (int mt = 0; mt < 2; mt++)
#pragma unroll
        for (int nt = 0; nt < 8; nt++)
#pragma unroll
            for (int i = 0; i < 4; i++) acc[mt][nt][i] = 0.f;

    auto load_tiles = [&](int buf, int k0) {
        __half* base = smf + buf * 10240;
#pragma unroll
        for (int r = 0; r < 4; r++) {
            int i = tid + 256 * r;          // 0..1023
            int mat = i >> 9;               // 0 A, 1 W
            int idx = i & 511;
            int row = idx >> 2, cu = idx & 3;
            const __half* gb = mat ? W : A;
            int rowbase = mat ? n0 : m0;
            const __half* gp = gb + (size_t)(rowbase + row) * K + k0 + cu * 8;
            u32 sdst = (u32)__cvta_generic_to_shared(base + mat * 5120 + row * 40 + cu * 8);
            CP_ASYNC16(sdst, gp);
        }
        CP_COMMIT();
    };

    load_tiles(0, 0);
    const int KT = K / 32;
    for (int kt = 0; kt < KT; kt++) {
        CP_WAIT(0);
        __syncthreads();
        if (kt + 1 < KT) load_tiles((kt + 1) & 1, (kt + 1) * 32);

        const u32 sb = s0 + (kt & 1) * 20480;   // bytes

#pragma unroll
        for (int ks = 0; ks < 2; ks++) {
            u32 af[2][4];
#pragma unroll
            for (int mt = 0; mt < 2; mt++) {
                u32 ao = sb + (u32)(((wm * 32 + mt * 16 + la) * 40 + ks * 16 + ha * 8) * 2);
                ldsm_x4(af[mt], ao);
            }
#pragma unroll
            for (int p = 0; p < 4; p++) {
                u32 bo = sb + 10240 +
                         (u32)(((wn * 64 + p * 16 + lb) * 40 + ks * 16 + kb) * 2);
                u32 b4[4];
                ldsm_x4(b4, bo);
#pragma unroll
                for (int half = 0; half < 2; half++) {
                    int nt = p * 2 + half;
#pragma unroll
                    for (int mt = 0; mt < 2; mt++)
                        mma_f16(acc[mt][nt], af[mt], b4[half * 2], b4[half * 2 + 1]);
                }
            }
        }
        __syncthreads();
    }

#pragma unroll
    for (int mt = 0; mt < 2; mt++) {
#pragma unroll
        for (int nt = 0; nt < 8; nt++) {
            int r0 = m0 + wm * 32 + mt * 16 + g;
            int c0 = n0 + wn * 64 + nt * 8 + tg * 2;
            float b0 = bias[c0], b1 = bias[c0 + 1];
            *(float2*)(Cf + (size_t)r0 * Nn + c0) =
                make_float2(acc[mt][nt][0] + b0, acc[mt][nt][1] + b1);
            *(float2*)(Cf + (size_t)(r0 + 8) * Nn + c0) =
                make_float2(acc[mt][nt][2] + b0, acc[mt][nt][3] + b1);
        }
    }
}

// ---------------- fused attention (all fp16 operands) ------------------------
// Per CTA: 32 q rows of one (b,h). 512 threads = 16 warps.
// smem: qf 0 (4608) | sc 4608 (131584) | kt 136192 (2 x 18432) | rinv 173056 (128)
#define AT_QF   0
#define AT_SC   4608
#define AT_KT   136192
#define AT_RINV 173056
#define AT_SMEM_BYTES 173184
#define SCS 2056       // score row stride (fp16 elems)
#define KTSTR 72       // kv tile row stride (elems)
#define KT_BUF (128 * KTSTR)
#define NT (SS / 128)  // 16 j-tiles

__global__ void __launch_bounds__(512) attn_kernel(
    const __half* __restrict__ qkvf,
    float* __restrict__ attnw,
    __half* __restrict__ of_g)
{
    extern __shared__ __align__(16) char smraw[];
    __half* qf = (__half*)(smraw + AT_QF);
    __half* sc = (__half*)(smraw + AT_SC);
    __half* kt = (__half*)(smraw + AT_KT);
    float* rinv = (float*)(smraw + AT_RINV);

    const int tid = threadIdx.x;
    const int warp = tid >> 5, lane = tid & 31;
    const int g = lane >> 2, tg = lane & 3;
    const int b = blockIdx.z, h = blockIdx.y;
    const int q0 = blockIdx.x * 32;
    const int tokq = b * SS + q0;

    const u32 s_qf = (u32)__cvta_generic_to_shared(qf);
    const u32 s_sc = (u32)__cvta_generic_to_shared(sc);
    const u32 s_kt = (u32)__cvta_generic_to_shared(kt);

    // one 128x64 fp16 tile (K or V depending on colb)
    auto load_tile = [&](int buf, int tok0, int colb) {
#pragma unroll
        for (int r = 0; r < 2; r++) {
            int i = tid + 512 * r;          // 0..1023
            int row = i >> 3, cu = i & 7;
            const __half* gp = qkvf + (size_t)(tok0 + row) * F3 + colb + cu * 8;
            u32 sd = s_kt + (buf * KT_BUF + row * KTSTR + cu * 8) * 2;
            CP_ASYNC16(sd, gp);
        }
        CP_COMMIT();
    };

    // ---- load Q tile (32x64 fp16) ----
    if (tid < 256) {
        int r = tid >> 3, cu = tid & 7;
        uint4 v = *(const uint4*)(qkvf + (size_t)(tokq + r) * F3 + h * HD + cu * 8);
        *(uint4*)(qf + r * KTSTR + cu * 8) = v;
    }
    load_tile(0, b * SS, EE + h * HD);   // K tile 0
    __syncthreads();

    // ---- preload Q fragments ----
    const int arow = lane & 15, asel = lane >> 4;
    u32 qfr[2][4][4];
#pragma unroll
    for (int ms = 0; ms < 2; ms++)
#pragma unroll
        for (int ks = 0; ks < 4; ks++) {
            u32 off = (u32)((ms * 16 + arow) * KTSTR + ks * 16 + asel * 8) * 2;
            ldsm_x4(qfr[ms][ks], s_qf + off);
        }

    // ================= phase 1: scores + exp -> fp16 smem =================
    const int n0 = warp * 8;
    const int brow = n0 + (lane & 7);
    const int bsel = (lane >> 3) & 1;
    for (int jt = 0; jt < NT; jt++) {
        if (jt + 1 < NT) {
            load_tile((jt + 1) & 1, b * SS + (jt + 1) * 128, EE + h * HD);
            CP_WAIT(1);
        } else {
            CP_WAIT(0);
        }
        __syncthreads();

        int buf = jt & 1;
        float acc[2][4] = {{0.f,0.f,0.f,0.f},{0.f,0.f,0.f,0.f}};
#pragma unroll
        for (int ks = 0; ks < 4; ks++) {
            u32 boff = (u32)(buf * KT_BUF + brow * KTSTR + ks * 16 + bsel * 8) * 2;
            u32 b0, b1;
            ldsm_x2(b0, b1, s_kt + boff);
            mma_f16(acc[0], qfr[0][ks], b0, b1);
            mma_f16(acc[1], qfr[1][ks], b0, b1);
        }
        {
            int col = jt * 128 + n0 + tg * 2;
#pragma unroll
            for (int ms = 0; ms < 2; ms++) {
                float e0 = __expf(acc[ms][0] * QK_SCALE);
                float e1 = __expf(acc[ms][1] * QK_SCALE);
                float e2 = __expf(acc[ms][2] * QK_SCALE);
                float e3 = __expf(acc[ms][3] * QK_SCALE);
                *(u32*)(sc + (ms * 16 + g) * SCS + col)     = packh2(e0, e1);
                *(u32*)(sc + (ms * 16 + g + 8) * SCS + col) = packh2(e2, e3);
            }
        }
        __syncthreads();
    }

    load_tile(0, b * SS, 2 * EE + h * HD);   // prefetch V tile 0

    // ================= phase 2: row sums =================
    {
#pragma unroll
        for (int half = 0; half < 2; half++) {
            int r = warp + half * 16;
            float s = 0.f;
            for (int j = lane * 4; j < SS; j += 128) {
                uint2 v = *(const uint2*)(sc + r * SCS + j);
                float2 a = h2f2(v.x), c = h2f2(v.y);
                s += (a.x + a.y) + (c.x + c.y);
            }
#pragma unroll
            for (int o = 16; o > 0; o >>= 1) s += __shfl_xor_sync(0xFFFFFFFFu, s, o);
            if (lane == 0) rinv[r] = 1.f / s;
        }
    }
    __syncthreads();

    // ================= phase 3+4: PV MMA with fused weight writes ==========
    const int wm = warp >> 3, wn = warp & 7;
    float acc4[4] = {0.f, 0.f, 0.f, 0.f};
    float* wbase = attnw + ((size_t)(b * HH + h) * SS + q0) * SS;
    const int wr = tid >> 4;            // 0..31 (weights row)
    const int wc = (tid & 15) * 8;      // 0..120 (weights col base)
    const float invr = rinv[wr];

    for (int jt = 0; jt < NT; jt++) {
        if (jt + 1 < NT) {
            load_tile((jt + 1) & 1, b * SS + (jt + 1) * 128, 2 * EE + h * HD);
            CP_WAIT(1);
        } else {
            CP_WAIT(0);
        }
        __syncthreads();

        int buf = jt & 1;
#pragma unroll
        for (int ks = 0; ks < 8; ks++) {
            u32 aoff = (u32)((wm * 16 + arow) * SCS + jt * 128 + ks * 16 + asel * 8) * 2;
            u32 af[4];
            ldsm_x4(af, s_sc + aoff);
            u32 boff = (u32)(buf * KT_BUF + (ks * 16 + arow) * KTSTR + wn * 8) * 2;
            u32 b0, b1;
            ldsm_x2t(b0, b1, s_kt + boff);
            mma_f16(acc4, af, b0, b1);
        }
        // fused normalized-weights write for this j-tile (overlaps with MMA/HBM)
        {
            const __half* sp = sc + (size_t)wr * SCS + jt * 128 + wc;
            uint4 v = *(const uint4*)sp;
            float2 a = h2f2(v.x), b2 = h2f2(v.y), c2 = h2f2(v.z), d2 = h2f2(v.w);
            float* dst = wbase + (size_t)wr * SS + jt * 128 + wc;
            *(float4*)dst       = make_float4(a.x * invr, a.y * invr, b2.x * invr, b2.y * invr);
            *(float4*)(dst + 4) = make_float4(c2.x * invr, c2.y * invr, d2.x * invr, d2.y * invr);
        }
        __syncthreads();
    }

    // epilogue: normalize, write single fp16 attn-out
    {
        int r0 = wm * 16 + g;
        int c0 = h * HD + wn * 8 + tg * 2;
        float inv0 = rinv[r0], inv1 = rinv[r0 + 8];
        *(u32*)(of_g + (size_t)(tokq + r0) * EE + c0)     = packh2(acc4[0] * inv0, acc4[1] * inv0);
        *(u32*)(of_g + (size_t)(tokq + r0 + 8) * EE + c0) = packh2(acc4[2] * inv1, acc4[3] * inv1);
    }
}

// ---------------------------------------------------------------------------
extern "C" void kernel_launch(void* const* d_in, const int* in_sizes, int n_in,
                              void* d_out, int out_size)
{
    const float* query = (const float*)d_in[0];
    const float* in_w  = (const float*)d_in[3];
    const float* in_b  = (const float*)d_in[4];
    const float* out_w = (const float*)d_in[5];
    const float* out_b = (const float*)d_in[6];

    float* out   = (float*)d_out;
    float* attnw = out + (size_t)NN * EE;

    void* p;
    bf16 *xh, *xl, *wih, *wil;
    __half *wof, *qkvf, *af;
    cudaGetSymbolAddress(&p, g_xh);   xh   = (bf16*)p;
    cudaGetSymbolAddress(&p, g_xl);   xl   = (bf16*)p;
    cudaGetSymbolAddress(&p, g_wih);  wih  = (bf16*)p;
    cudaGetSymbolAddress(&p, g_wil);  wil  = (bf16*)p;
    cudaGetSymbolAddress(&p, g_wof);  wof  = (__half*)p;
    cudaGetSymbolAddress(&p, g_qkvf); qkvf = (__half*)p;
    cudaGetSymbolAddress(&p, g_af);   af   = (__half*)p;

    static int attr_done = 0;
    if (!attr_done) {
        cudaFuncSetAttribute(gemm_bf16x3, cudaFuncAttributeMaxDynamicSharedMemorySize,
                             GEMM_SMEM_BYTES);
        cudaFuncSetAttribute(gemm_f16, cudaFuncAttributeMaxDynamicSharedMemorySize,
                             GEMMF_SMEM_BYTES);
        cudaFuncSetAttribute(attn_kernel, cudaFuncAttributeMaxDynamicSharedMemorySize,
                             AT_SMEM_BYTES);
        attr_done = 1;
    }

    // splits / conversions
    split_kernel<<<(NN * EE) / 1024, 256>>>(query, xh, xl);
    split_kernel<<<(F3 * EE) / 1024, 256>>>(in_w, wih, wil);
    fconv_kernel<<<(EE * EE) / 1024, 256>>>(out_w, wof);

    // QKV projection -> fp16 qkv
    {
        dim3 grid(F3 / 128, NN / 128);
        gemm_bf16x3<<<grid, 256, GEMM_SMEM_BYTES>>>(
            xh, xl, wih, wil, in_b, qkvf, NN, F3, EE);
    }

    // fused attention (writes attn_weights directly + fp16 attn-out)
    {
        dim3 grid(SS / 32, HH, BB);
        attn_kernel<<<grid, 512, AT_SMEM_BYTES>>>(qkvf, attnw, af);
    }

    // out projection (single fp16 term) -> fp32 d_out
    {
        dim3 grid(EE / 128, NN / 128);
        gemm_f16<<<grid, 256, GEMMF_SMEM_BYTES>>>(
            af, wof, out_b, out, NN, EE, EE);
    }
}

// round 9
// speedup vs baseline: 11.9297x; 1.2490x over previous
#include <cuda_runtime.h>
#include <cuda_bf16.h>
#include <cuda_fp16.h>
#include <math.h>

#define BB 2
#define SS 2048
#define EE 1024
#define HH 16
#define HD 64
#define NN (BB*SS)       // 4096 tokens
#define F3 (3*EE)        // 3072
#define QK_SCALE 0.125f

typedef unsigned int u32;

// ---------------- scratch (device globals; no runtime allocation) ----------
__device__ __half g_xf[(size_t)NN * EE];    // query fp16
__device__ __half g_wif[(size_t)F3 * EE];   // in_proj_w fp16
__device__ __half g_wof[(size_t)EE * EE];   // out_proj_w fp16
__device__ __half g_qkvf[(size_t)NN * F3];  // qkv fp16
__device__ __half g_af[(size_t)NN * EE];    // attn out fp16

// ---------------- helpers --------------------------------------------------
__device__ __forceinline__ u32 packh2(float a, float b) {
    __half2 h = __floats2half2_rn(a, b);
    return *(u32*)&h;
}
__device__ __forceinline__ float2 h2f2(u32 u) {
    __half2 v = *(__half2*)&u;
    return __half22float2(v);
}
__device__ __forceinline__ void mma_f16(float* d, const u32* a, u32 b0, u32 b1) {
    asm volatile(
        "mma.sync.aligned.m16n8k16.row.col.f32.f16.f16.f32 "
        "{%0,%1,%2,%3},{%4,%5,%6,%7},{%8,%9},{%0,%1,%2,%3};"
        : "+f"(d[0]), "+f"(d[1]), "+f"(d[2]), "+f"(d[3])
        : "r"(a[0]), "r"(a[1]), "r"(a[2]), "r"(a[3]), "r"(b0), "r"(b1));
}
__device__ __forceinline__ void ldsm_x4(u32* r, u32 addr) {
    asm volatile("ldmatrix.sync.aligned.m8n8.x4.shared.b16 {%0,%1,%2,%3}, [%4];"
        : "=r"(r[0]), "=r"(r[1]), "=r"(r[2]), "=r"(r[3]) : "r"(addr));
}
__device__ __forceinline__ void ldsm_x2(u32& r0, u32& r1, u32 addr) {
    asm volatile("ldmatrix.sync.aligned.m8n8.x2.shared.b16 {%0,%1}, [%2];"
        : "=r"(r0), "=r"(r1) : "r"(addr));
}
__device__ __forceinline__ void ldsm_x2t(u32& r0, u32& r1, u32 addr) {
    asm volatile("ldmatrix.sync.aligned.m8n8.x2.trans.shared.b16 {%0,%1}, [%2];"
        : "=r"(r0), "=r"(r1) : "r"(addr));
}
#define CP_ASYNC16(sdst, gsrc) \
    asm volatile("cp.async.cg.shared.global [%0], [%1], 16;" :: "r"(sdst), "l"(gsrc))
#define CP_COMMIT() asm volatile("cp.async.commit_group;")
#define CP_WAIT(n)  asm volatile("cp.async.wait_group %0;" :: "n"(n))

// ---------------- fconv: fp32 -> fp16 ---------------------------------------
__global__ void __launch_bounds__(256) fconv_kernel(
    const float* __restrict__ x, __half* __restrict__ y)
{
    int i = (blockIdx.x * 256 + threadIdx.x) * 4;
    float4 v = *(const float4*)(x + i);
    *(uint2*)(y + i) = make_uint2(packh2(v.x, v.y), packh2(v.z, v.w));
}

// ---------------- fp16 GEMM (NT): C = A[M,K] * W[N,K]^T + bias --------------
// BM=BN=128, BK=32, 256 thr (8 warps: 4m x 2n), warp tile 32x64, 2-stage.
// outmode 0: fp32 out (Cf); outmode 1: fp16 out (Ch).
#define GEMMF_SMEM_BYTES (2 * 2 * 128 * 40 * 2)  // 40960

__global__ void __launch_bounds__(256, 2) gemm_f16(
    const __half* __restrict__ A, const __half* __restrict__ W,
    const float* __restrict__ bias,
    float* __restrict__ Cf, __half* __restrict__ Ch,
    int M, int Nn, int K, int outmode)
{
    extern __shared__ __align__(16) __half smf[];
    const int tid = threadIdx.x;
    const int warp = tid >> 5, lane = tid & 31;
    const int g = lane >> 2, tg = lane & 3;
    const int wm = warp >> 1, wn = warp & 1;
    const int m0 = blockIdx.y * 128, n0 = blockIdx.x * 128;
    const u32 s0 = (u32)__cvta_generic_to_shared(smf);

    const int la = lane & 15, ha = lane >> 4;
    const int lb = (lane & 7) + ((lane >> 4) << 3);
    const int kb = ((lane >> 3) & 1) * 8;

    float acc[2][8][4];
#pragma unroll
    for (int mt = 0; mt < 2; mt++)
#pragma unroll
        for (int nt = 0; nt < 8; nt++)
#pragma unroll
            for (int i = 0; i < 4; i++) acc[mt][nt][i] = 0.f;

    auto load_tiles = [&](int buf, int k0) {
        __half* base = smf + buf * 10240;
#pragma unroll
        for (int r = 0; r < 4; r++) {
            int i = tid + 256 * r;          // 0..1023
            int mat = i >> 9;               // 0 A, 1 W
            int idx = i & 511;
            int row = idx >> 2, cu = idx & 3;
            const __half* gb = mat ? W : A;
            int rowbase = mat ? n0 : m0;
            const __half* gp = gb + (size_t)(rowbase + row) * K + k0 + cu * 8;
            u32 sdst = (u32)__cvta_generic_to_shared(base + mat * 5120 + row * 40 + cu * 8);
            CP_ASYNC16(sdst, gp);
        }
        CP_COMMIT();
    };

    load_tiles(0, 0);
    const int KT = K / 32;
    for (int kt = 0; kt < KT; kt++) {
        CP_WAIT(0);
        __syncthreads();
        if (kt + 1 < KT) load_tiles((kt + 1) & 1, (kt + 1) * 32);

        const u32 sb = s0 + (kt & 1) * 20480;   // bytes

#pragma unroll
        for (int ks = 0; ks < 2; ks++) {
            u32 af[2][4];
#pragma unroll
            for (int mt = 0; mt < 2; mt++) {
                u32 ao = sb + (u32)(((wm * 32 + mt * 16 + la) * 40 + ks * 16 + ha * 8) * 2);
                ldsm_x4(af[mt], ao);
            }
#pragma unroll
            for (int p = 0; p < 4; p++) {
                u32 bo = sb + 10240 +
                         (u32)(((wn * 64 + p * 16 + lb) * 40 + ks * 16 + kb) * 2);
                u32 b4[4];
                ldsm_x4(b4, bo);
#pragma unroll
                for (int half = 0; half < 2; half++) {
                    int nt = p * 2 + half;
#pragma unroll
                    for (int mt = 0; mt < 2; mt++)
                        mma_f16(acc[mt][nt], af[mt], b4[half * 2], b4[half * 2 + 1]);
                }
            }
        }
        __syncthreads();
    }

#pragma unroll
    for (int mt = 0; mt < 2; mt++) {
#pragma unroll
        for (int nt = 0; nt < 8; nt++) {
            int r0 = m0 + wm * 32 + mt * 16 + g;
            int c0 = n0 + wn * 64 + nt * 8 + tg * 2;
            float b0 = bias[c0], b1 = bias[c0 + 1];
            float v00 = acc[mt][nt][0] + b0, v01 = acc[mt][nt][1] + b1;
            float v10 = acc[mt][nt][2] + b0, v11 = acc[mt][nt][3] + b1;
            if (outmode == 0) {
                *(float2*)(Cf + (size_t)r0 * Nn + c0)       = make_float2(v00, v01);
                *(float2*)(Cf + (size_t)(r0 + 8) * Nn + c0) = make_float2(v10, v11);
            } else {
                *(u32*)(Ch + (size_t)r0 * Nn + c0)       = packh2(v00, v01);
                *(u32*)(Ch + (size_t)(r0 + 8) * Nn + c0) = packh2(v10, v11);
            }
        }
    }
}

// ---------------- fused attention (all fp16 operands) ------------------------
// Per CTA: 32 q rows of one (b,h). 512 threads = 16 warps.
// smem: qf 0 (4608) | sc 4608 (131584) | kt 136192 (2 x 18432) | rinv 173056 (128)
#define AT_QF   0
#define AT_SC   4608
#define AT_KT   136192
#define AT_RINV 173056
#define AT_SMEM_BYTES 173184
#define SCS 2056       // score row stride (fp16 elems)
#define KTSTR 72       // kv tile row stride (elems)
#define KT_BUF (128 * KTSTR)
#define NT (SS / 128)  // 16 j-tiles

__global__ void __launch_bounds__(512) attn_kernel(
    const __half* __restrict__ qkvf,
    float* __restrict__ attnw,
    __half* __restrict__ of_g)
{
    extern __shared__ __align__(16) char smraw[];
    __half* qf = (__half*)(smraw + AT_QF);
    __half* sc = (__half*)(smraw + AT_SC);
    __half* kt = (__half*)(smraw + AT_KT);
    float* rinv = (float*)(smraw + AT_RINV);

    const int tid = threadIdx.x;
    const int warp = tid >> 5, lane = tid & 31;
    const int g = lane >> 2, tg = lane & 3;
    const int b = blockIdx.z, h = blockIdx.y;
    const int q0 = blockIdx.x * 32;
    const int tokq = b * SS + q0;

    const u32 s_qf = (u32)__cvta_generic_to_shared(qf);
    const u32 s_sc = (u32)__cvta_generic_to_shared(sc);
    const u32 s_kt = (u32)__cvta_generic_to_shared(kt);

    auto load_tile = [&](int buf, int tok0, int colb) {
#pragma unroll
        for (int r = 0; r < 2; r++) {
            int i = tid + 512 * r;          // 0..1023
            int row = i >> 3, cu = i & 7;
            const __half* gp = qkvf + (size_t)(tok0 + row) * F3 + colb + cu * 8;
            u32 sd = s_kt + (buf * KT_BUF + row * KTSTR + cu * 8) * 2;
            CP_ASYNC16(sd, gp);
        }
        CP_COMMIT();
    };

    // ---- load Q tile (32x64 fp16) ----
    if (tid < 256) {
        int r = tid >> 3, cu = tid & 7;
        uint4 v = *(const uint4*)(qkvf + (size_t)(tokq + r) * F3 + h * HD + cu * 8);
        *(uint4*)(qf + r * KTSTR + cu * 8) = v;
    }
    load_tile(0, b * SS, EE + h * HD);   // K tile 0
    __syncthreads();

    // ---- preload Q fragments ----
    const int arow = lane & 15, asel = lane >> 4;
    u32 qfr[2][4][4];
#pragma unroll
    for (int ms = 0; ms < 2; ms++)
#pragma unroll
        for (int ks = 0; ks < 4; ks++) {
            u32 off = (u32)((ms * 16 + arow) * KTSTR + ks * 16 + asel * 8) * 2;
            ldsm_x4(qfr[ms][ks], s_qf + off);
        }

    // ================= phase 1: scores + exp -> fp16 smem =================
    const int n0 = warp * 8;
    const int brow = n0 + (lane & 7);
    const int bsel = (lane >> 3) & 1;
    for (int jt = 0; jt < NT; jt++) {
        if (jt + 1 < NT) {
            load_tile((jt + 1) & 1, b * SS + (jt + 1) * 128, EE + h * HD);
            CP_WAIT(1);
        } else {
            CP_WAIT(0);
        }
        __syncthreads();

        int buf = jt & 1;
        float acc[2][4] = {{0.f,0.f,0.f,0.f},{0.f,0.f,0.f,0.f}};
#pragma unroll
        for (int ks = 0; ks < 4; ks++) {
            u32 boff = (u32)(buf * KT_BUF + brow * KTSTR + ks * 16 + bsel * 8) * 2;
            u32 b0, b1;
            ldsm_x2(b0, b1, s_kt + boff);
            mma_f16(acc[0], qfr[0][ks], b0, b1);
            mma_f16(acc[1], qfr[1][ks], b0, b1);
        }
        {
            int col = jt * 128 + n0 + tg * 2;
#pragma unroll
            for (int ms = 0; ms < 2; ms++) {
                float e0 = __expf(acc[ms][0] * QK_SCALE);
                float e1 = __expf(acc[ms][1] * QK_SCALE);
                float e2 = __expf(acc[ms][2] * QK_SCALE);
                float e3 = __expf(acc[ms][3] * QK_SCALE);
                *(u32*)(sc + (ms * 16 + g) * SCS + col)     = packh2(e0, e1);
                *(u32*)(sc + (ms * 16 + g + 8) * SCS + col) = packh2(e2, e3);
            }
        }
        __syncthreads();
    }

    load_tile(0, b * SS, 2 * EE + h * HD);   // prefetch V tile 0

    // ================= phase 2: row sums =================
    {
#pragma unroll
        for (int half = 0; half < 2; half++) {
            int r = warp + half * 16;
            float s = 0.f;
            for (int j = lane * 4; j < SS; j += 128) {
                uint2 v = *(const uint2*)(sc + r * SCS + j);
                float2 a = h2f2(v.x), c = h2f2(v.y);
                s += (a.x + a.y) + (c.x + c.y);
            }
#pragma unroll
            for (int o = 16; o > 0; o >>= 1) s += __shfl_xor_sync(0xFFFFFFFFu, s, o);
            if (lane == 0) rinv[r] = 1.f / s;
        }
    }
    __syncthreads();

    // ================= phase 3+4: PV MMA with fused weight writes ==========
    const int wm = warp >> 3, wn = warp & 7;
    float acc4[4] = {0.f, 0.f, 0.f, 0.f};
    float* wbase = attnw + ((size_t)(b * HH + h) * SS + q0) * SS;
    const int wr = tid >> 4;            // 0..31 (weights row)
    const int wc = (tid & 15) * 8;      // 0..120 (weights col base)
    const float invr = rinv[wr];

    for (int jt = 0; jt < NT; jt++) {
        if (jt + 1 < NT) {
            load_tile((jt + 1) & 1, b * SS + (jt + 1) * 128, 2 * EE + h * HD);
            CP_WAIT(1);
        } else {
            CP_WAIT(0);
        }
        __syncthreads();

        int buf = jt & 1;
#pragma unroll
        for (int ks = 0; ks < 8; ks++) {
            u32 aoff = (u32)((wm * 16 + arow) * SCS + jt * 128 + ks * 16 + asel * 8) * 2;
            u32 af[4];
            ldsm_x4(af, s_sc + aoff);
            u32 boff = (u32)(buf * KT_BUF + (ks * 16 + arow) * KTSTR + wn * 8) * 2;
            u32 b0, b1;
            ldsm_x2t(b0, b1, s_kt + boff);
            mma_f16(acc4, af, b0, b1);
        }
        // fused normalized-weights write for this j-tile
        {
            const __half* sp = sc + (size_t)wr * SCS + jt * 128 + wc;
            uint4 v = *(const uint4*)sp;
            float2 a = h2f2(v.x), b2 = h2f2(v.y), c2 = h2f2(v.z), d2 = h2f2(v.w);
            float* dst = wbase + (size_t)wr * SS + jt * 128 + wc;
            *(float4*)dst       = make_float4(a.x * invr, a.y * invr, b2.x * invr, b2.y * invr);
            *(float4*)(dst + 4) = make_float4(c2.x * invr, c2.y * invr, d2.x * invr, d2.y * invr);
        }
        __syncthreads();
    }

    // epilogue: normalize, write single fp16 attn-out
    {
        int r0 = wm * 16 + g;
        int c0 = h * HD + wn * 8 + tg * 2;
        float inv0 = rinv[r0], inv1 = rinv[r0 + 8];
        *(u32*)(of_g + (size_t)(tokq + r0) * EE + c0)     = packh2(acc4[0] * inv0, acc4[1] * inv0);
        *(u32*)(of_g + (size_t)(tokq + r0 + 8) * EE + c0) = packh2(acc4[2] * inv1, acc4[3] * inv1);
    }
}

// ---------------------------------------------------------------------------
extern "C" void kernel_launch(void* const* d_in, const int* in_sizes, int n_in,
                              void* d_out, int out_size)
{
    const float* query = (const float*)d_in[0];
    const float* in_w  = (const float*)d_in[3];
    const float* in_b  = (const float*)d_in[4];
    const float* out_w = (const float*)d_in[5];
    const float* out_b = (const float*)d_in[6];

    float* out   = (float*)d_out;
    float* attnw = out + (size_t)NN * EE;

    void* p;
    __half *xf, *wif, *wof, *qkvf, *af;
    cudaGetSymbolAddress(&p, g_xf);   xf   = (__half*)p;
    cudaGetSymbolAddress(&p, g_wif);  wif  = (__half*)p;
    cudaGetSymbolAddress(&p, g_wof);  wof  = (__half*)p;
    cudaGetSymbolAddress(&p, g_qkvf); qkvf = (__half*)p;
    cudaGetSymbolAddress(&p, g_af);   af   = (__half*)p;

    static int attr_done = 0;
    if (!attr_done) {
        cudaFuncSetAttribute(gemm_f16, cudaFuncAttributeMaxDynamicSharedMemorySize,
                             GEMMF_SMEM_BYTES);
        cudaFuncSetAttribute(attn_kernel, cudaFuncAttributeMaxDynamicSharedMemorySize,
                             AT_SMEM_BYTES);
        attr_done = 1;
    }

    // conversions to fp16
    fconv_kernel<<<(NN * EE) / 1024, 256>>>(query, xf);
    fconv_kernel<<<(F3 * EE) / 1024, 256>>>(in_w, wif);
    fconv_kernel<<<(EE * EE) / 1024, 256>>>(out_w, wof);

    // QKV projection (fp16) -> fp16 qkv
    {
        dim3 grid(F3 / 128, NN / 128);
        gemm_f16<<<grid, 256, GEMMF_SMEM_BYTES>>>(
            xf, wif, in_b, nullptr, qkvf, NN, F3, EE, 1);
    }

    // fused attention (writes attn_weights directly + fp16 attn-out)
    {
        dim3 grid(SS / 32, HH, BB);
        attn_kernel<<<grid, 512, AT_SMEM_BYTES>>>(qkvf, attnw, af);
    }

    // out projection (fp16) -> fp32 d_out
    {
        dim3 grid(EE / 128, NN / 128);
        gemm_f16<<<grid, 256, GEMMF_SMEM_BYTES>>>(
            af, wof, out_b, out, nullptr, NN, EE, EE, 0);
    }
}

// round 11
// speedup vs baseline: 12.4953x; 1.0474x over previous
#include <cuda_runtime.h>
#include <cuda_bf16.h>
#include <cuda_fp16.h>
#include <math.h>

#define BB 2
#define SS 2048
#define EE 1024
#define HH 16
#define HD 64
#define NN (BB*SS)       // 4096 tokens
#define F3 (3*EE)        // 3072
#define QK_SCALE 0.125f

typedef unsigned int u32;

// ---------------- scratch (device globals; no runtime allocation) ----------
__device__ __half g_xf[(size_t)NN * EE];    // query fp16
__device__ __half g_wif[(size_t)F3 * EE];   // in_proj_w fp16
__device__ __half g_wof[(size_t)EE * EE];   // out_proj_w fp16
__device__ __half g_qkvf[(size_t)NN * F3];  // qkv fp16
__device__ __half g_af[(size_t)NN * EE];    // attn out fp16

// ---------------- helpers --------------------------------------------------
__device__ __forceinline__ u32 packh2(float a, float b) {
    __half2 h = __floats2half2_rn(a, b);
    return *(u32*)&h;
}
__device__ __forceinline__ float2 h2f2(u32 u) {
    __half2 v = *(__half2*)&u;
    return __half22float2(v);
}
__device__ __forceinline__ void mma_f16(float* d, const u32* a, u32 b0, u32 b1) {
    asm volatile(
        "mma.sync.aligned.m16n8k16.row.col.f32.f16.f16.f32 "
        "{%0,%1,%2,%3},{%4,%5,%6,%7},{%8,%9},{%0,%1,%2,%3};"
        : "+f"(d[0]), "+f"(d[1]), "+f"(d[2]), "+f"(d[3])
        : "r"(a[0]), "r"(a[1]), "r"(a[2]), "r"(a[3]), "r"(b0), "r"(b1));
}
__device__ __forceinline__ void ldsm_x4(u32* r, u32 addr) {
    asm volatile("ldmatrix.sync.aligned.m8n8.x4.shared.b16 {%0,%1,%2,%3}, [%4];"
        : "=r"(r[0]), "=r"(r[1]), "=r"(r[2]), "=r"(r[3]) : "r"(addr));
}
__device__ __forceinline__ void ldsm_x2t(u32& r0, u32& r1, u32 addr) {
    asm volatile("ldmatrix.sync.aligned.m8n8.x2.trans.shared.b16 {%0,%1}, [%2];"
        : "=r"(r0), "=r"(r1) : "r"(addr));
}
#define CP_ASYNC16(sdst, gsrc) \
    asm volatile("cp.async.cg.shared.global [%0], [%1], 16;" :: "r"(sdst), "l"(gsrc))
#define CP_COMMIT() asm volatile("cp.async.commit_group;")
#define CP_WAIT(n)  asm volatile("cp.async.wait_group %0;" :: "n"(n))

// ---------------- fconv: fp32 -> fp16 ---------------------------------------
__global__ void __launch_bounds__(256) fconv_kernel(
    const float* __restrict__ x, __half* __restrict__ y)
{
    int i = (blockIdx.x * 256 + threadIdx.x) * 4;
    float4 v = *(const float4*)(x + i);
    *(uint2*)(y + i) = make_uint2(packh2(v.x, v.y), packh2(v.z, v.w));
}

// ---------------- fp16 GEMM (NT): C = A[M,K] * W[N,K]^T + bias --------------
// BM=BN=128, BK=32, 256 thr (8 warps: 4m x 2n), warp tile 32x64, 2-stage.
// outmode 0: fp32 out (Cf); outmode 1: fp16 out (Ch).
#define GEMMF_SMEM_BYTES (2 * 2 * 128 * 40 * 2)  // 40960

__global__ void __launch_bounds__(256, 2) gemm_f16(
    const __half* __restrict__ A, const __half* __restrict__ W,
    const float* __restrict__ bias,
    float* __restrict__ Cf, __half* __restrict__ Ch,
    int M, int Nn, int K, int outmode)
{
    extern __shared__ __align__(16) __half smf[];
    const int tid = threadIdx.x;
    const int warp = tid >> 5, lane = tid & 31;
    const int g = lane >> 2, tg = lane & 3;
    const int wm = warp >> 1, wn = warp & 1;
    const int m0 = blockIdx.y * 128, n0 = blockIdx.x * 128;
    const u32 s0 = (u32)__cvta_generic_to_shared(smf);

    const int la = lane & 15, ha = lane >> 4;
    const int lb = (lane & 7) + ((lane >> 4) << 3);
    const int kb = ((lane >> 3) & 1) * 8;

    float acc[2][8][4];
#pragma unroll
    for (int mt = 0; mt < 2; mt++)
#pragma unroll
        for (int nt = 0; nt < 8; nt++)
#pragma unroll
            for (int i = 0; i < 4; i++) acc[mt][nt][i] = 0.f;

    auto load_tiles = [&](int buf, int k0) {
        __half* base = smf + buf * 10240;
#pragma unroll
        for (int r = 0; r < 4; r++) {
            int i = tid + 256 * r;          // 0..1023
            int mat = i >> 9;               // 0 A, 1 W
            int idx = i & 511;
            int row = idx >> 2, cu = idx & 3;
            const __half* gb = mat ? W : A;
            int rowbase = mat ? n0 : m0;
            const __half* gp = gb + (size_t)(rowbase + row) * K + k0 + cu * 8;
            u32 sdst = (u32)__cvta_generic_to_shared(base + mat * 5120 + row * 40 + cu * 8);
            CP_ASYNC16(sdst, gp);
        }
        CP_COMMIT();
    };

    load_tiles(0, 0);
    const int KT = K / 32;
    for (int kt = 0; kt < KT; kt++) {
        CP_WAIT(0);
        __syncthreads();
        if (kt + 1 < KT) load_tiles((kt + 1) & 1, (kt + 1) * 32);

        const u32 sb = s0 + (kt & 1) * 20480;   // bytes

#pragma unroll
        for (int ks = 0; ks < 2; ks++) {
            u32 af[2][4];
#pragma unroll
            for (int mt = 0; mt < 2; mt++) {
                u32 ao = sb + (u32)(((wm * 32 + mt * 16 + la) * 40 + ks * 16 + ha * 8) * 2);
                ldsm_x4(af[mt], ao);
            }
#pragma unroll
            for (int p = 0; p < 4; p++) {
                u32 bo = sb + 10240 +
                         (u32)(((wn * 64 + p * 16 + lb) * 40 + ks * 16 + kb) * 2);
                u32 b4[4];
                ldsm_x4(b4, bo);
#pragma unroll
                for (int half = 0; half < 2; half++) {
                    int nt = p * 2 + half;
#pragma unroll
                    for (int mt = 0; mt < 2; mt++)
                        mma_f16(acc[mt][nt], af[mt], b4[half * 2], b4[half * 2 + 1]);
                }
            }
        }
        __syncthreads();
    }

#pragma unroll
    for (int mt = 0; mt < 2; mt++) {
#pragma unroll
        for (int nt = 0; nt < 8; nt++) {
            int r0 = m0 + wm * 32 + mt * 16 + g;
            int c0 = n0 + wn * 64 + nt * 8 + tg * 2;
            float b0 = bias[c0], b1 = bias[c0 + 1];
            float v00 = acc[mt][nt][0] + b0, v01 = acc[mt][nt][1] + b1;
            float v10 = acc[mt][nt][2] + b0, v11 = acc[mt][nt][3] + b1;
            if (outmode == 0) {
                *(float2*)(Cf + (size_t)r0 * Nn + c0)       = make_float2(v00, v01);
                *(float2*)(Cf + (size_t)(r0 + 8) * Nn + c0) = make_float2(v10, v11);
            } else {
                *(u32*)(Ch + (size_t)r0 * Nn + c0)       = packh2(v00, v01);
                *(u32*)(Ch + (size_t)(r0 + 8) * Nn + c0) = packh2(v10, v11);
            }
        }
    }
}

// ---------------- fused attention v4: M=16, 256 thr, 2 CTAs/SM --------------
// smem: qf 0 (2304) | sc 2304 (65792) | kt 68096 (2 x 18432) | rinv 104960 (64)
#define AT_QF   0
#define AT_SC   2304
#define AT_KT   68096
#define AT_RINV 104960
#define AT_SMEM_BYTES 105024
#define SCS 2056       // score row stride (fp16 elems)
#define KTSTR 72       // kv tile row stride (elems)
#define KT_BUF (128 * KTSTR)
#define NT (SS / 128)  // 16 j-tiles

__global__ void __launch_bounds__(256, 2) attn_kernel(
    const __half* __restrict__ qkvf,
    float* __restrict__ attnw,
    __half* __restrict__ of_g)
{
    extern __shared__ __align__(16) char smraw[];
    __half* qf = (__half*)(smraw + AT_QF);
    __half* sc = (__half*)(smraw + AT_SC);
    __half* kt = (__half*)(smraw + AT_KT);
    float* rinv = (float*)(smraw + AT_RINV);

    const int tid = threadIdx.x;
    const int warp = tid >> 5, lane = tid & 31;
    const int g = lane >> 2, tg = lane & 3;
    const int b = blockIdx.z, h = blockIdx.y;
    const int q0 = blockIdx.x * 16;
    const int tokq = b * SS + q0;

    const u32 s_qf = (u32)__cvta_generic_to_shared(qf);
    const u32 s_sc = (u32)__cvta_generic_to_shared(sc);
    const u32 s_kt = (u32)__cvta_generic_to_shared(kt);

    // one 128x64 fp16 tile (K or V depending on colb); 1024 chunks / 256 thr
    auto load_tile = [&](int buf, int tok0, int colb) {
#pragma unroll
        for (int r = 0; r < 4; r++) {
            int i = tid + 256 * r;          // 0..1023
            int row = i >> 3, cu = i & 7;
            const __half* gp = qkvf + (size_t)(tok0 + row) * F3 + colb + cu * 8;
            u32 sd = s_kt + (buf * KT_BUF + row * KTSTR + cu * 8) * 2;
            CP_ASYNC16(sd, gp);
        }
        CP_COMMIT();
    };

    // ---- load Q tile (16x64 fp16): 128 chunks ----
    if (tid < 128) {
        int r = tid >> 3, cu = tid & 7;
        uint4 v = *(const uint4*)(qkvf + (size_t)(tokq + r) * F3 + h * HD + cu * 8);
        *(uint4*)(qf + r * KTSTR + cu * 8) = v;
    }
    load_tile(0, b * SS, EE + h * HD);   // K tile 0
    __syncthreads();

    // ---- preload Q fragments (m16 x k16 x 4 k-steps) ----
    const int arow = lane & 15, asel = lane >> 4;
    u32 qfr[4][4];
#pragma unroll
    for (int ks = 0; ks < 4; ks++) {
        u32 off = (u32)(arow * KTSTR + ks * 16 + asel * 8) * 2;
        ldsm_x4(qfr[ks], s_qf + off);
    }

    // ================= phase 1: scores + exp -> fp16 smem =================
    // each warp owns 16 key columns: n0..n0+15
    const int n0 = warp * 16;
    // B ldsm_x4 lane mapping: 4 8x8 mats = (n-half 0/1) x (k-half 0/1)
    const int bbrow = n0 + ((lane >> 4) << 3) + (lane & 7);
    const int bbcol = ((lane >> 3) & 1) * 8;
    for (int jt = 0; jt < NT; jt++) {
        if (jt + 1 < NT) {
            load_tile((jt + 1) & 1, b * SS + (jt + 1) * 128, EE + h * HD);
            CP_WAIT(1);
        } else {
            CP_WAIT(0);
        }
        __syncthreads();

        int buf = jt & 1;
        float acc[2][4] = {{0.f,0.f,0.f,0.f},{0.f,0.f,0.f,0.f}};
#pragma unroll
        for (int ks = 0; ks < 4; ks++) {
            u32 boff = (u32)(buf * KT_BUF + bbrow * KTSTR + ks * 16 + bbcol) * 2;
            u32 b4[4];
            ldsm_x4(b4, s_kt + boff);
            mma_f16(acc[0], qfr[ks], b4[0], b4[1]);   // cols n0..n0+7
            mma_f16(acc[1], qfr[ks], b4[2], b4[3]);   // cols n0+8..n0+15
        }
        {
#pragma unroll
            for (int nb = 0; nb < 2; nb++) {
                int col = jt * 128 + n0 + nb * 8 + tg * 2;
                float e0 = __expf(acc[nb][0] * QK_SCALE);
                float e1 = __expf(acc[nb][1] * QK_SCALE);
                float e2 = __expf(acc[nb][2] * QK_SCALE);
                float e3 = __expf(acc[nb][3] * QK_SCALE);
                *(u32*)(sc + g * SCS + col)       = packh2(e0, e1);
                *(u32*)(sc + (g + 8) * SCS + col) = packh2(e2, e3);
            }
        }
        __syncthreads();
    }

    load_tile(0, b * SS, 2 * EE + h * HD);   // prefetch V tile 0

    // ================= phase 2: row sums (8 warps x 2 rows) =================
    {
#pragma unroll
        for (int half = 0; half < 2; half++) {
            int r = warp + half * 8;
            float s = 0.f;
            for (int j = lane * 4; j < SS; j += 128) {
                uint2 v = *(const uint2*)(sc + r * SCS + j);
                float2 a = h2f2(v.x), c = h2f2(v.y);
                s += (a.x + a.y) + (c.x + c.y);
            }
#pragma unroll
            for (int o = 16; o > 0; o >>= 1) s += __shfl_xor_sync(0xFFFFFFFFu, s, o);
            if (lane == 0) rinv[r] = 1.f / s;
        }
    }
    __syncthreads();

    // ================= phase 3+4: PV MMA with fused weight writes ==========
    const int wn = warp;                 // 8 warps x 8 cols = HD 64
    float acc4[4] = {0.f, 0.f, 0.f, 0.f};
    float* wbase = attnw + ((size_t)(b * HH + h) * SS + q0) * SS;
    const int wr = tid >> 4;             // 0..15 (weights row)
    const int wc = (tid & 15) * 8;       // 0..120 (weights col base)
    const float invr = rinv[wr];

    for (int jt = 0; jt < NT; jt++) {
        if (jt + 1 < NT) {
            load_tile((jt + 1) & 1, b * SS + (jt + 1) * 128, 2 * EE + h * HD);
            CP_WAIT(1);
        } else {
            CP_WAIT(0);
        }
        __syncthreads();

        int buf = jt & 1;
#pragma unroll
        for (int ks = 0; ks < 8; ks++) {
            u32 aoff = (u32)(arow * SCS + jt * 128 + ks * 16 + asel * 8) * 2;
            u32 af[4];
            ldsm_x4(af, s_sc + aoff);
            u32 boff = (u32)(buf * KT_BUF + (ks * 16 + arow) * KTSTR + wn * 8) * 2;
            u32 b0, b1;
            ldsm_x2t(b0, b1, s_kt + boff);
            mma_f16(acc4, af, b0, b1);
        }
        // fused normalized-weights write for this j-tile
        {
            const __half* sp = sc + (size_t)wr * SCS + jt * 128 + wc;
            uint4 v = *(const uint4*)sp;
            float2 a = h2f2(v.x), b2 = h2f2(v.y), c2 = h2f2(v.z), d2 = h2f2(v.w);
            float* dst = wbase + (size_t)wr * SS + jt * 128 + wc;
            *(float4*)dst       = make_float4(a.x * invr, a.y * invr, b2.x * invr, b2.y * invr);
            *(float4*)(dst + 4) = make_float4(c2.x * invr, c2.y * invr, d2.x * invr, d2.y * invr);
        }
        __syncthreads();
    }

    // epilogue: normalize, write single fp16 attn-out
    {
        int c0 = h * HD + wn * 8 + tg * 2;
        float inv0 = rinv[g], inv1 = rinv[g + 8];
        *(u32*)(of_g + (size_t)(tokq + g) * EE + c0)     = packh2(acc4[0] * inv0, acc4[1] * inv0);
        *(u32*)(of_g + (size_t)(tokq + g + 8) * EE + c0) = packh2(acc4[2] * inv1, acc4[3] * inv1);
    }
}

// ---------------------------------------------------------------------------
extern "C" void kernel_launch(void* const* d_in, const int* in_sizes, int n_in,
                              void* d_out, int out_size)
{
    const float* query = (const float*)d_in[0];
    const float* in_w  = (const float*)d_in[3];
    const float* in_b  = (const float*)d_in[4];
    const float* out_w = (const float*)d_in[5];
    const float* out_b = (const float*)d_in[6];

    float* out   = (float*)d_out;
    float* attnw = out + (size_t)NN * EE;

    void* p;
    __half *xf, *wif, *wof, *qkvf, *af;
    cudaGetSymbolAddress(&p, g_xf);   xf   = (__half*)p;
    cudaGetSymbolAddress(&p, g_wif);  wif  = (__half*)p;
    cudaGetSymbolAddress(&p, g_wof);  wof  = (__half*)p;
    cudaGetSymbolAddress(&p, g_qkvf); qkvf = (__half*)p;
    cudaGetSymbolAddress(&p, g_af);   af   = (__half*)p;

    static int attr_done = 0;
    if (!attr_done) {
        cudaFuncSetAttribute(gemm_f16, cudaFuncAttributeMaxDynamicSharedMemorySize,
                             GEMMF_SMEM_BYTES);
        cudaFuncSetAttribute(attn_kernel, cudaFuncAttributeMaxDynamicSharedMemorySize,
                             AT_SMEM_BYTES);
        attr_done = 1;
    }

    // conversions to fp16
    fconv_kernel<<<(NN * EE) / 1024, 256>>>(query, xf);
    fconv_kernel<<<(F3 * EE) / 1024, 256>>>(in_w, wif);
    fconv_kernel<<<(EE * EE) / 1024, 256>>>(out_w, wof);

    // QKV projection (fp16) -> fp16 qkv
    {
        dim3 grid(F3 / 128, NN / 128);
        gemm_f16<<<grid, 256, GEMMF_SMEM_BYTES>>>(
            xf, wif, in_b, nullptr, qkvf, NN, F3, EE, 1);
    }

    // fused attention (writes attn_weights directly + fp16 attn-out)
    {
        dim3 grid(SS / 16, HH, BB);
        attn_kernel<<<grid, 256, AT_SMEM_BYTES>>>(qkvf, attnw, af);
    }

    // out projection (fp16) -> fp32 d_out
    {
        dim3 grid(EE / 128, NN / 128);
        gemm_f16<<<grid, 256, GEMMF_SMEM_BYTES>>>(
            af, wof, out_b, out, nullptr, NN, EE, EE, 0);
    }
}

// round 14
// speedup vs baseline: 15.8734x; 1.2703x over previous
#include <cuda_runtime.h>
#include <cuda_bf16.h>
#include <cuda_fp16.h>
#include <math.h>

#define BB 2
#define SS 2048
#define EE 1024
#define HH 16
#define HD 64
#define NN (BB*SS)       // 4096 tokens
#define F3 (3*EE)        // 3072
#define QK_SCALE 0.125f

typedef unsigned int u32;

// ---------------- scratch (device globals; no runtime allocation) ----------
__device__ __half g_xf[(size_t)NN * EE];    // query fp16
__device__ __half g_wif[(size_t)F3 * EE];   // in_proj_w fp16
__device__ __half g_wof[(size_t)EE * EE];   // out_proj_w fp16
__device__ __half g_qkvf[(size_t)NN * F3];  // qkv fp16
__device__ __half g_af[(size_t)NN * EE];    // attn out fp16
__device__ __half g_scr[(size_t)BB * HH * SS * SS];  // exp(scores) fp16 (268MB)

// ---------------- helpers --------------------------------------------------
__device__ __forceinline__ u32 packh2(float a, float b) {
    __half2 h = __floats2half2_rn(a, b);
    return *(u32*)&h;
}
__device__ __forceinline__ float2 h2f2(u32 u) {
    __half2 v = *(__half2*)&u;
    return __half22float2(v);
}
__device__ __forceinline__ void mma_f16(float* d, const u32* a, u32 b0, u32 b1) {
    asm volatile(
        "mma.sync.aligned.m16n8k16.row.col.f32.f16.f16.f32 "
        "{%0,%1,%2,%3},{%4,%5,%6,%7},{%8,%9},{%0,%1,%2,%3};"
        : "+f"(d[0]), "+f"(d[1]), "+f"(d[2]), "+f"(d[3])
        : "r"(a[0]), "r"(a[1]), "r"(a[2]), "r"(a[3]), "r"(b0), "r"(b1));
}
__device__ __forceinline__ void ldsm_x4(u32* r, u32 addr) {
    asm volatile("ldmatrix.sync.aligned.m8n8.x4.shared.b16 {%0,%1,%2,%3}, [%4];"
        : "=r"(r[0]), "=r"(r[1]), "=r"(r[2]), "=r"(r[3]) : "r"(addr));
}
__device__ __forceinline__ void ldsm_x2t(u32& r0, u32& r1, u32 addr) {
    asm volatile("ldmatrix.sync.aligned.m8n8.x2.trans.shared.b16 {%0,%1}, [%2];"
        : "=r"(r0), "=r"(r1) : "r"(addr));
}
#define CP_ASYNC16(sdst, gsrc) \
    asm volatile("cp.async.cg.shared.global [%0], [%1], 16;" :: "r"(sdst), "l"(gsrc))
#define CP_COMMIT() asm volatile("cp.async.commit_group;")
#define CP_WAIT(n)  asm volatile("cp.async.wait_group %0;" :: "n"(n))

// ---------------- fconv: fp32 -> fp16 ---------------------------------------
__global__ void __launch_bounds__(256) fconv_kernel(
    const float* __restrict__ x, __half* __restrict__ y)
{
    int i = (blockIdx.x * 256 + threadIdx.x) * 4;
    float4 v = *(const float4*)(x + i);
    *(uint2*)(y + i) = make_uint2(packh2(v.x, v.y), packh2(v.z, v.w));
}

// ---------------- fp16 GEMM (NT): C = A[M,K] * W[N,K]^T + bias --------------
#define GEMMF_SMEM_BYTES (2 * 2 * 128 * 40 * 2)  // 40960

__global__ void __launch_bounds__(256, 2) gemm_f16(
    const __half* __restrict__ A, const __half* __restrict__ W,
    const float* __restrict__ bias,
    float* __restrict__ Cf, __half* __restrict__ Ch,
    int M, int Nn, int K, int outmode)
{
    extern __shared__ __align__(16) __half smf[];
    const int tid = threadIdx.x;
    const int warp = tid >> 5, lane = tid & 31;
    const int g = lane >> 2, tg = lane & 3;
    const int wm = warp >> 1, wn = warp & 1;
    const int m0 = blockIdx.y * 128, n0 = blockIdx.x * 128;
    const u32 s0 = (u32)__cvta_generic_to_shared(smf);

    const int la = lane & 15, ha = lane >> 4;
    const int lb = (lane & 7) + ((lane >> 4) << 3);
    const int kb = ((lane >> 3) & 1) * 8;

    float acc[2][8][4];
#pragma unroll
    for (int mt = 0; mt < 2; mt++)
#pragma unroll
        for (int nt = 0; nt < 8; nt++)
#pragma unroll
            for (int i = 0; i < 4; i++) acc[mt][nt][i] = 0.f;

    auto load_tiles = [&](int buf, int k0) {
        __half* base = smf + buf * 10240;
#pragma unroll
        for (int r = 0; r < 4; r++) {
            int i = tid + 256 * r;
            int mat = i >> 9;
            int idx = i & 511;
            int row = idx >> 2, cu = idx & 3;
            const __half* gb = mat ? W : A;
            int rowbase = mat ? n0 : m0;
            const __half* gp = gb + (size_t)(rowbase + row) * K + k0 + cu * 8;
            u32 sdst = (u32)__cvta_generic_to_shared(base + mat * 5120 + row * 40 + cu * 8);
            CP_ASYNC16(sdst, gp);
        }
        CP_COMMIT();
    };

    load_tiles(0, 0);
    const int KT = K / 32;
    for (int kt = 0; kt < KT; kt++) {
        CP_WAIT(0);
        __syncthreads();
        if (kt + 1 < KT) load_tiles((kt + 1) & 1, (kt + 1) * 32);

        const u32 sb = s0 + (kt & 1) * 20480;

#pragma unroll
        for (int ks = 0; ks < 2; ks++) {
            u32 af[2][4];
#pragma unroll
            for (int mt = 0; mt < 2; mt++) {
                u32 ao = sb + (u32)(((wm * 32 + mt * 16 + la) * 40 + ks * 16 + ha * 8) * 2);
                ldsm_x4(af[mt], ao);
            }
#pragma unroll
            for (int p = 0; p < 4; p++) {
                u32 bo = sb + 10240 +
                         (u32)(((wn * 64 + p * 16 + lb) * 40 + ks * 16 + kb) * 2);
                u32 b4[4];
                ldsm_x4(b4, bo);
#pragma unroll
                for (int half = 0; half < 2; half++) {
                    int nt = p * 2 + half;
#pragma unroll
                    for (int mt = 0; mt < 2; mt++)
                        mma_f16(acc[mt][nt], af[mt], b4[half * 2], b4[half * 2 + 1]);
                }
            }
        }
        __syncthreads();
    }

#pragma unroll
    for (int mt = 0; mt < 2; mt++) {
#pragma unroll
        for (int nt = 0; nt < 8; nt++) {
            int r0 = m0 + wm * 32 + mt * 16 + g;
            int c0 = n0 + wn * 64 + nt * 8 + tg * 2;
            float b0 = bias[c0], b1 = bias[c0 + 1];
            float v00 = acc[mt][nt][0] + b0, v01 = acc[mt][nt][1] + b1;
            float v10 = acc[mt][nt][2] + b0, v11 = acc[mt][nt][3] + b1;
            if (outmode == 0) {
                *(float2*)(Cf + (size_t)r0 * Nn + c0)       = make_float2(v00, v01);
                *(float2*)(Cf + (size_t)(r0 + 8) * Nn + c0) = make_float2(v10, v11);
            } else {
                *(u32*)(Ch + (size_t)r0 * Nn + c0)       = packh2(v00, v01);
                *(u32*)(Ch + (size_t)(r0 + 8) * Nn + c0) = packh2(v10, v11);
            }
        }
    }
}

// ---------------- fused attention v5: M=64, 256 thr, global score scratch ---
// smem (bytes): qf 0 (9216) | kt 9216 (2 x 18432) | st 46080 (2 x 17408)
//               rsum 80896 (2048) | rinv 82944 (256)    total 83200
#define ATP_QF   0
#define ATP_KT   9216
#define ATP_ST   46080
#define ATP_RSUM 80896
#define ATP_RINV 82944
#define ATP_SMEM 83200
#define KTSTR 72
#define KT_BUF (128 * KTSTR)   // 9216 elems
#define STSTR 136
#define ST_BUF (64 * STSTR)    // 8704 elems
#define NT (SS / 128)          // 16 j-tiles

__global__ void __launch_bounds__(256, 2) attn_kernel(
    const __half* __restrict__ qkvf,
    __half* __restrict__ scr,
    float* __restrict__ attnw,
    __half* __restrict__ of_g)
{
    extern __shared__ __align__(16) char smraw[];
    __half* qf  = (__half*)(smraw + ATP_QF);
    __half* kt  = (__half*)(smraw + ATP_KT);
    __half* st  = (__half*)(smraw + ATP_ST);
    float* rsum = (float*)(smraw + ATP_RSUM);
    float* rinv = (float*)(smraw + ATP_RINV);

    const int tid = threadIdx.x;
    const int warp = tid >> 5, lane = tid & 31;
    const int g = lane >> 2, tg = lane & 3;
    const int b = blockIdx.z, h = blockIdx.y;
    const int q0 = blockIdx.x * 64;
    const int tokq = b * SS + q0;
    const size_t scrbase = ((size_t)(b * HH + h) * SS + q0) * SS;

    const u32 s_qf = (u32)__cvta_generic_to_shared(qf);
    const u32 s_kt = (u32)__cvta_generic_to_shared(kt);
    const u32 s_st = (u32)__cvta_generic_to_shared(st);

    // K tile: 128x64 fp16
    auto load_k = [&](int buf, int jt) {
        int tok0 = b * SS + jt * 128;
        int colb = EE + h * HD;
#pragma unroll
        for (int r = 0; r < 4; r++) {
            int i = tid + 256 * r;          // 0..1023
            int row = i >> 3, cu = i & 7;
            const __half* gp = qkvf + (size_t)(tok0 + row) * F3 + colb + cu * 8;
            u32 sd = s_kt + (buf * KT_BUF + row * KTSTR + cu * 8) * 2;
            CP_ASYNC16(sd, gp);
        }
        CP_COMMIT();
    };
    // V tile + score tile (one commit group)
    auto load_vs = [&](int buf, int jt) {
        int tok0 = b * SS + jt * 128;
        int colb = 2 * EE + h * HD;
#pragma unroll
        for (int r = 0; r < 4; r++) {
            int i = tid + 256 * r;
            int row = i >> 3, cu = i & 7;
            const __half* gp = qkvf + (size_t)(tok0 + row) * F3 + colb + cu * 8;
            u32 sd = s_kt + (buf * KT_BUF + row * KTSTR + cu * 8) * 2;
            CP_ASYNC16(sd, gp);
        }
#pragma unroll
        for (int r = 0; r < 4; r++) {
            int i = tid + 256 * r;          // 0..1023
            int row = i >> 4, cu = i & 15;  // 64 rows x 16 chunks
            const __half* gp = scr + scrbase + (size_t)row * SS + jt * 128 + cu * 8;
            u32 sd = s_st + (buf * ST_BUF + row * STSTR + cu * 8) * 2;
            CP_ASYNC16(sd, gp);
        }
        CP_COMMIT();
    };

    // ---- load Q tile (64x64 fp16): 512 chunks ----
#pragma unroll
    for (int r = 0; r < 2; r++) {
        int i = tid + 256 * r;
        int row = i >> 3, cu = i & 7;
        uint4 v = *(const uint4*)(qkvf + (size_t)(tokq + row) * F3 + h * HD + cu * 8);
        *(uint4*)(qf + row * KTSTR + cu * 8) = v;
    }
    load_k(0, 0);
    __syncthreads();

    // ---- preload Q fragments: 4 m-frags x 4 k-steps x 4 regs ----
    const int arow = lane & 15, asel = lane >> 4;
    u32 qfr[4][4][4];
#pragma unroll
    for (int mf = 0; mf < 4; mf++)
#pragma unroll
        for (int ks = 0; ks < 4; ks++) {
            u32 off = (u32)((mf * 16 + arow) * KTSTR + ks * 16 + asel * 8) * 2;
            ldsm_x4(qfr[mf][ks], s_qf + off);
        }

    // ================= pass 1: scores -> exp -> scratch + rowsums ==========
    const int n0 = warp * 16;
    const int bbrow = n0 + ((lane >> 4) << 3) + (lane & 7);
    const int bbcol = ((lane >> 3) & 1) * 8;
    float rs[4][2];
#pragma unroll
    for (int mf = 0; mf < 4; mf++) { rs[mf][0] = 0.f; rs[mf][1] = 0.f; }

    for (int jt = 0; jt < NT; jt++) {
        if (jt + 1 < NT) {
            load_k((jt + 1) & 1, jt + 1);
            CP_WAIT(1);
        } else {
            CP_WAIT(0);
        }
        __syncthreads();

        int buf = jt & 1;
#pragma unroll
        for (int mf = 0; mf < 4; mf++) {
            float acc[2][4] = {{0.f,0.f,0.f,0.f},{0.f,0.f,0.f,0.f}};
#pragma unroll
            for (int ks = 0; ks < 4; ks++) {
                u32 boff = (u32)(buf * KT_BUF + bbrow * KTSTR + ks * 16 + bbcol) * 2;
                u32 b4[4];
                ldsm_x4(b4, s_kt + boff);
                mma_f16(acc[0], qfr[mf][ks], b4[0], b4[1]);
                mma_f16(acc[1], qfr[mf][ks], b4[2], b4[3]);
            }
#pragma unroll
            for (int nb = 0; nb < 2; nb++) {
                int col = n0 + nb * 8 + tg * 2;
                float e0 = __expf(acc[nb][0] * QK_SCALE);
                float e1 = __expf(acc[nb][1] * QK_SCALE);
                float e2 = __expf(acc[nb][2] * QK_SCALE);
                float e3 = __expf(acc[nb][3] * QK_SCALE);
                rs[mf][0] += e0 + e1;
                rs[mf][1] += e2 + e3;
                *(u32*)(st + (mf * 16 + g) * STSTR + col)     = packh2(e0, e1);
                *(u32*)(st + (mf * 16 + g + 8) * STSTR + col) = packh2(e2, e3);
            }
        }
        __syncthreads();
        // staged tile -> scratch (coalesced)
#pragma unroll
        for (int r = 0; r < 4; r++) {
            int i = tid + 256 * r;
            int row = i >> 4, cu = i & 15;
            *(uint4*)(scr + scrbase + (size_t)row * SS + jt * 128 + cu * 8) =
                *(const uint4*)(st + row * STSTR + cu * 8);
        }
        __syncthreads();
    }

    // prefetch V+scores tile 0 (overlaps the rowsum reduction)
    load_vs(0, 0);

    // ---- rowsum reduce -> rinv ----
    {
#pragma unroll
        for (int mf = 0; mf < 4; mf++)
#pragma unroll
            for (int half = 0; half < 2; half++) {
                float s = rs[mf][half];
                s += __shfl_xor_sync(0xFFFFFFFFu, s, 1);
                s += __shfl_xor_sync(0xFFFFFFFFu, s, 2);
                if (tg == 0) rsum[(mf * 16 + g + half * 8) * 8 + warp] = s;
            }
    }
    __syncthreads();
    if (tid < 64) {
        float s = 0.f;
#pragma unroll
        for (int w = 0; w < 8; w++) s += rsum[tid * 8 + w];
        rinv[tid] = 1.f / s;
    }
    __syncthreads();

    // ================= pass 2: PV MMA + fused weights write ================
    const int wn = warp;                 // 8 warps x 8 HD cols
    const int wid = tid >> 5;
    float invw[8];
#pragma unroll
    for (int r = 0; r < 8; r++) invw[r] = rinv[wid + 8 * r];

    float acc4[4][4];
#pragma unroll
    for (int mf = 0; mf < 4; mf++)
#pragma unroll
        for (int i = 0; i < 4; i++) acc4[mf][i] = 0.f;

    float* wbase = attnw + scrbase;      // same indexing as scratch, fp32

    for (int jt = 0; jt < NT; jt++) {
        if (jt + 1 < NT) {
            load_vs((jt + 1) & 1, jt + 1);
            CP_WAIT(1);
        } else {
            CP_WAIT(0);
        }
        __syncthreads();

        int buf = jt & 1;
#pragma unroll
        for (int ks = 0; ks < 8; ks++) {
            u32 boff = (u32)(buf * KT_BUF + (ks * 16 + arow) * KTSTR + wn * 8) * 2;
            u32 b0, b1;
            ldsm_x2t(b0, b1, s_kt + boff);
#pragma unroll
            for (int mf = 0; mf < 4; mf++) {
                u32 aoff = (u32)(buf * ST_BUF + (mf * 16 + arow) * STSTR + ks * 16 + asel * 8) * 2;
                u32 af[4];
                ldsm_x4(af, s_st + aoff);
                mma_f16(acc4[mf], af, b0, b1);
            }
        }
        // fused normalized weights write for this j-tile
#pragma unroll
        for (int r = 0; r < 8; r++) {
            int i = tid + 256 * r;
            int row = i >> 5;                // wid + 8r
            int c4 = (i & 31) * 4;
            uint2 v = *(const uint2*)(st + buf * ST_BUF + row * STSTR + c4);
            float2 a = h2f2(v.x), b2 = h2f2(v.y);
            float inv = invw[r];
            *(float4*)(wbase + (size_t)row * SS + jt * 128 + c4) =
                make_float4(a.x * inv, a.y * inv, b2.x * inv, b2.y * inv);
        }
        __syncthreads();
    }

    // epilogue: normalize PV accumulators, write fp16 attn-out
    {
        int c0 = h * HD + wn * 8 + tg * 2;
#pragma unroll
        for (int mf = 0; mf < 4; mf++) {
            int r0 = mf * 16 + g;
            float inv0 = rinv[r0], inv1 = rinv[r0 + 8];
            *(u32*)(of_g + (size_t)(tokq + r0) * EE + c0) =
                packh2(acc4[mf][0] * inv0, acc4[mf][1] * inv0);
            *(u32*)(of_g + (size_t)(tokq + r0 + 8) * EE + c0) =
                packh2(acc4[mf][2] * inv1, acc4[mf][3] * inv1);
        }
    }
}

// ---------------------------------------------------------------------------
extern "C" void kernel_launch(void* const* d_in, const int* in_sizes, int n_in,
                              void* d_out, int out_size)
{
    const float* query = (const float*)d_in[0];
    const float* in_w  = (const float*)d_in[3];
    const float* in_b  = (const float*)d_in[4];
    const float* out_w = (const float*)d_in[5];
    const float* out_b = (const float*)d_in[6];

    float* out   = (float*)d_out;
    float* attnw = out + (size_t)NN * EE;

    void* p;
    __half *xf, *wif, *wof, *qkvf, *af, *scr;
    cudaGetSymbolAddress(&p, g_xf);   xf   = (__half*)p;
    cudaGetSymbolAddress(&p, g_wif);  wif  = (__half*)p;
    cudaGetSymbolAddress(&p, g_wof);  wof  = (__half*)p;
    cudaGetSymbolAddress(&p, g_qkvf); qkvf = (__half*)p;
    cudaGetSymbolAddress(&p, g_af);   af   = (__half*)p;
    cudaGetSymbolAddress(&p, g_scr);  scr  = (__half*)p;

    static int attr_done = 0;
    if (!attr_done) {
        cudaFuncSetAttribute(gemm_f16, cudaFuncAttributeMaxDynamicSharedMemorySize,
                             GEMMF_SMEM_BYTES);
        cudaFuncSetAttribute(attn_kernel, cudaFuncAttributeMaxDynamicSharedMemorySize,
                             ATP_SMEM);
        attr_done = 1;
    }

    // conversions to fp16
    fconv_kernel<<<(NN * EE) / 1024, 256>>>(query, xf);
    fconv_kernel<<<(F3 * EE) / 1024, 256>>>(in_w, wif);
    fconv_kernel<<<(EE * EE) / 1024, 256>>>(out_w, wof);

    // QKV projection (fp16) -> fp16 qkv
    {
        dim3 grid(F3 / 128, NN / 128);
        gemm_f16<<<grid, 256, GEMMF_SMEM_BYTES>>>(
            xf, wif, in_b, nullptr, qkvf, NN, F3, EE, 1);
    }

    // fused attention (M=64, scratch-backed scores)
    {
        dim3 grid(SS / 64, HH, BB);
        attn_kernel<<<grid, 256, ATP_SMEM>>>(qkvf, scr, attnw, af);
    }

    // out projection (fp16) -> fp32 d_out
    {
        dim3 grid(EE / 128, NN / 128);
        gemm_f16<<<grid, 256, GEMMF_SMEM_BYTES>>>(
            af, wof, out_b, out, nullptr, NN, EE, EE, 0);
    }
}